// round 8
// baseline (speedup 1.0000x reference)
#include <cuda_runtime.h>
#include <cuda_bf16.h>
#include <cstdint>
#include <math.h>

#define BATCH  4
#define SEQ    2048
#define DMODEL 512
#define NHEADS 8
#define DHEAD  64
#define DFF    2048
#define NBLOCKS 6
#define NROWS  (BATCH * SEQ)

// ---------------------------------------------------------------------------
// Scratch.  All bf16-pair arrays are stored K-PAIR-PERMUTED: within each
// 16-pair (32-element) chunk, pair j sits at position
// (j&8)|((j&3)<<1)|((j>>2)&1).  Fragment loads then hit adjacent u32s.
// ---------------------------------------------------------------------------
__device__ float    g_h  [NROWS * DMODEL];
__device__ float    g_y  [NROWS * DMODEL];
__device__ float    g_a  [NROWS * DMODEL];
__device__ uint32_t g_hhi [NROWS * 256],  g_hlo [NROWS * 256];
__device__ uint32_t g_yhi [NROWS * 256],  g_ylo [NROWS * 256];
__device__ uint32_t g_aohi[NROWS * 256],  g_aolo[NROWS * 256];
__device__ uint32_t g_midhi[NROWS * 1024], g_midlo[NROWS * 1024];
__device__ uint32_t g_qhi[BATCH*NHEADS*SEQ*32], g_qlo[BATCH*NHEADS*SEQ*32];
__device__ uint32_t g_khi[BATCH*NHEADS*SEQ*32], g_klo[BATCH*NHEADS*SEQ*32];
__device__ __nv_bfloat16 g_vhi[BATCH*NHEADS*DHEAD*SEQ], g_vlo[BATCH*NHEADS*DHEAD*SEQ];
__device__ uint32_t g_wqkv_hi[NBLOCKS*1536*256], g_wqkv_lo[NBLOCKS*1536*256];
__device__ uint32_t g_w0_hi [NBLOCKS*512*256],  g_w0_lo [NBLOCKS*512*256];
__device__ uint32_t g_l1_hi [NBLOCKS*2048*256], g_l1_lo [NBLOCKS*2048*256];
__device__ uint32_t g_l2_hi [NBLOCKS*512*1024], g_l2_lo [NBLOCKS*512*1024];

__device__ __forceinline__ int pperm(int jg) {
    int j = jg & 15;
    return (jg & ~15) | (j & 8) | ((j & 3) << 1) | ((j >> 2) & 1);
}
__device__ __forceinline__ int eperm(int t) {          // element (bf16) index
    return 2 * pperm(t >> 1) + (t & 1);
}

__device__ __forceinline__ float gelu_exact(float x) {
    return 0.5f * x * (1.0f + erff(x * 0.70710678118654752f));
}

__device__ __forceinline__ void split2(float x, float y, uint32_t& hi, uint32_t& lo) {
    __nv_bfloat16 hx = __float2bfloat16_rn(x);
    __nv_bfloat16 hy = __float2bfloat16_rn(y);
    float rx = x - __bfloat162float(hx);
    float ry = y - __bfloat162float(hy);
    __nv_bfloat162 H; H.x = hx; H.y = hy;
    __nv_bfloat162 L = __floats2bfloat162_rn(rx, ry);
    hi = *reinterpret_cast<uint32_t*>(&H);
    lo = *reinterpret_cast<uint32_t*>(&L);
}

__device__ __forceinline__ void mma_bf16(float* c, const uint32_t* a, const uint32_t* b) {
    asm volatile(
        "mma.sync.aligned.m16n8k16.row.col.f32.bf16.bf16.f32 "
        "{%0,%1,%2,%3}, {%4,%5,%6,%7}, {%8,%9}, {%0,%1,%2,%3};"
        : "+f"(c[0]), "+f"(c[1]), "+f"(c[2]), "+f"(c[3])
        : "r"(a[0]), "r"(a[1]), "r"(a[2]), "r"(a[3]), "r"(b[0]), "r"(b[1]));
}

__device__ __forceinline__ uint32_t smem_u32(const void* p) {
    uint32_t a;
    asm("{ .reg .u64 t; cvta.to.shared.u64 t, %1; cvt.u32.u64 %0, t; }"
        : "=r"(a) : "l"(p));
    return a;
}
__device__ __forceinline__ void cp16(uint32_t sa, const void* ga) {
    asm volatile("cp.async.ca.shared.global [%0], [%1], 16;" :: "r"(sa), "l"(ga));
}
#define CP_COMMIT() asm volatile("cp.async.commit_group;" ::: "memory")
#define CP_WAIT1()  asm volatile("cp.async.wait_group 1;" ::: "memory")

// ---------------------------------------------------------------------------
// Embedding + PE
// ---------------------------------------------------------------------------
__global__ void embed_k(const int* __restrict__ x, const float* __restrict__ E,
                        const float* __restrict__ pe, float* __restrict__ H,
                        uint32_t* __restrict__ Hhi, uint32_t* __restrict__ Hlo) {
    int idx = blockIdx.x * blockDim.x + threadIdx.x;
    int row = idx >> 7;
    int c   = (idx & 127) << 2;
    int t   = row & (SEQ - 1);
    int tok = x[row];
    float4 e = *(const float4*)(E  + (size_t)tok * DMODEL + c);
    float4 p = *(const float4*)(pe + (size_t)t   * DMODEL + c);
    float4 o = make_float4(e.x + p.x, e.y + p.y, e.z + p.z, e.w + p.w);
    *(float4*)(H + (size_t)row * DMODEL + c) = o;
    uint32_t h0, l0, h1, l1;
    split2(o.x, o.y, h0, l0);
    split2(o.z, o.w, h1, l1);
    int p0 = c >> 1;
    size_t rb = (size_t)row * 256;
    Hhi[rb + pperm(p0)]     = h0; Hlo[rb + pperm(p0)]     = l0;
    Hhi[rb + pperm(p0 + 1)] = h1; Hlo[rb + pperm(p0 + 1)] = l1;
}

// ---------------------------------------------------------------------------
// Weight transpose + split (permuted output)
// ---------------------------------------------------------------------------
__global__ void wtrans_k(const float* __restrict__ W, uint32_t* __restrict__ Whi,
                         uint32_t* __restrict__ Wlo, int K, int N) {
    __shared__ float t[32][33];
    int n0 = blockIdx.x * 32, k0 = blockIdx.y * 32;
    const float* Wz = W + (size_t)blockIdx.z * K * N;
    uint32_t* Whiz = Whi + (size_t)blockIdx.z * N * (K >> 1);
    uint32_t* Wloz = Wlo + (size_t)blockIdx.z * N * (K >> 1);
    int tx = threadIdx.x, ty = threadIdx.y;
    int tid = ty * 32 + tx;
#pragma unroll
    for (int i = 0; i < 32; i += 8)
        t[ty + i][tx] = Wz[(size_t)(k0 + ty + i) * N + n0 + tx];
    __syncthreads();
    int kp = tid & 15, nn = tid >> 4;
    int kpp = (kp & 8) | ((kp & 3) << 1) | ((kp >> 2) & 1);
#pragma unroll
    for (int j = 0; j < 2; j++) {
        int n = nn + 16 * j;
        uint32_t hi, lo;
        split2(t[2 * kp][n], t[2 * kp + 1][n], hi, lo);
        size_t oi = (size_t)(n0 + n) * (K >> 1) + (k0 >> 1) + kpp;
        Whiz[oi] = hi;
        Wloz[oi] = lo;
    }
}

// QKV weight: permuted column n' = kv*512+h*64+d; Q pre-scaled; K-pair permuted.
__global__ void wqkvtrans_k(const float* __restrict__ W,
                            uint32_t* __restrict__ Whi, uint32_t* __restrict__ Wlo) {
    int z   = blockIdx.y;
    int idx = blockIdx.x * 256 + threadIdx.x;    // over 1536*256
    int k2  = idx & 255;
    int np  = idx >> 8;
    int kv  = np >> 9, h = (np >> 6) & 7, d = np & 63;
    int n   = d * 24 + kv * 8 + h;
    const float* Wz = W + (size_t)z * 512 * 1536;
    float x0 = Wz[(size_t)(2 * k2) * 1536 + n];
    float x1 = Wz[(size_t)(2 * k2 + 1) * 1536 + n];
    if (kv == 0) { x0 *= 0.18033688011112042f; x1 *= 0.18033688011112042f; }
    uint32_t hi, lo;
    split2(x0, x1, hi, lo);
    size_t oi = (size_t)z * 1536 * 256 + (size_t)np * 256 + pperm(k2);
    Whi[oi] = hi;
    Wlo[oi] = lo;
}

// ---------------------------------------------------------------------------
// bf16x3 warp-MMA GEMM.  CTA 128x128, 8 warps (64x32), K-chunk 32.
// 2-stage cp.async, permuted layout, stride 24 u32, LDS.64 fragments.
// EPI: 0 plain->C, 1 +bias->C, 2 +bias+gelu->hi/lo, 3 QKV scatter
// ---------------------------------------------------------------------------
#define GROW 24
#define GTILE (128 * GROW)            // 3072 u32
#define GSTAGE (4 * GTILE)            // 12288 u32
#define GMM_SMEM (2 * GSTAGE * 4)     // 98304 B

template <int EPI>
__global__ void __launch_bounds__(256, 2) gemm_mma(
    const uint32_t* __restrict__ Ahi, const uint32_t* __restrict__ Alo,
    const uint32_t* __restrict__ Bhi, const uint32_t* __restrict__ Blo,
    const float* __restrict__ bias, float* __restrict__ C,
    uint32_t* __restrict__ O1h, uint32_t* __restrict__ O1l,
    uint32_t* __restrict__ O2h, uint32_t* __restrict__ O2l,
    __nv_bfloat16* __restrict__ O3h, __nv_bfloat16* __restrict__ O3l,
    int M, int N, int K)
{
    extern __shared__ uint32_t sm[];

    const int tid  = threadIdx.x;
    const int wid  = tid >> 5;
    const int lane = tid & 31;
    const int g    = lane >> 2;
    const int cq   = lane & 3;
    const int wm   = (wid & 1) * 64;
    const int wn   = (wid >> 1) * 32;
    const int m0   = blockIdx.y * 128;
    const int n0   = blockIdx.x * 128;
    const int K2   = K >> 1;
    const int NC   = K >> 5;
    const uint32_t sbase = smem_u32(sm);
    const int pu = tid & 3;
    const int pr = tid >> 2;

    auto issue = [&](int cc) {
        const uint32_t sb = sbase + (uint32_t)((cc & 1) * (GSTAGE * 4));
        const int k4 = cc << 4;
#pragma unroll
        for (int i = 0; i < 8; i++) {
            int r = pr + ((i & 1) << 6);
            int tile = i >> 1;
            const uint32_t* gp;
            if (tile == 0)      gp = Ahi + (size_t)(m0 + r) * K2;
            else if (tile == 1) gp = Alo + (size_t)(m0 + r) * K2;
            else if (tile == 2) gp = Bhi + (size_t)(n0 + r) * K2;
            else                gp = Blo + (size_t)(n0 + r) * K2;
            cp16(sb + (uint32_t)(tile * GTILE + r * GROW + pu * 4) * 4,
                 gp + k4 + pu * 4);
        }
    };

    float acc[4][4][4];
#pragma unroll
    for (int mt = 0; mt < 4; mt++)
#pragma unroll
        for (int nt = 0; nt < 4; nt++)
#pragma unroll
            for (int e = 0; e < 4; e++) acc[mt][nt][e] = 0.0f;

    issue(0); CP_COMMIT();

    for (int c = 0; c < NC; c++) {
        if (c + 1 < NC) issue(c + 1);
        CP_COMMIT();
        CP_WAIT1();
        __syncthreads();
        const uint32_t* sp = sm + (c & 1) * GSTAGE;

#pragma unroll
        for (int ks = 0; ks < 2; ks++) {
            const int kb = ks * 8 + 2 * cq;
            uint32_t bh[4][2], bl[4][2];
#pragma unroll
            for (int nt = 0; nt < 4; nt++) {
                int bi = 2 * GTILE + (wn + nt * 8 + g) * GROW + kb;
                uint2 vbh = *(const uint2*)&sp[bi];
                uint2 vbl = *(const uint2*)&sp[bi + GTILE];
                bh[nt][0] = vbh.x; bh[nt][1] = vbh.y;
                bl[nt][0] = vbl.x; bl[nt][1] = vbl.y;
            }
#pragma unroll
            for (int mt = 0; mt < 4; mt++) {
                int ai = (wm + mt * 16 + g) * GROW + kb;
                uint2 a0 = *(const uint2*)&sp[ai];
                uint2 a1 = *(const uint2*)&sp[ai + 8 * GROW];
                uint2 c0 = *(const uint2*)&sp[ai + GTILE];
                uint2 c1 = *(const uint2*)&sp[ai + GTILE + 8 * GROW];
                uint32_t ah[4] = {a0.x, a1.x, a0.y, a1.y};
                uint32_t al[4] = {c0.x, c1.x, c0.y, c1.y};
#pragma unroll
                for (int nt = 0; nt < 4; nt++) mma_bf16(acc[mt][nt], ah, bh[nt]);
#pragma unroll
                for (int nt = 0; nt < 4; nt++) mma_bf16(acc[mt][nt], al, bh[nt]);
#pragma unroll
                for (int nt = 0; nt < 4; nt++) mma_bf16(acc[mt][nt], ah, bl[nt]);
            }
        }
        __syncthreads();
    }

    // ---- epilogue ----
#pragma unroll
    for (int mt = 0; mt < 4; mt++) {
#pragma unroll
        for (int nt = 0; nt < 4; nt++) {
            int col = n0 + wn + nt * 8 + 2 * cq;
            int r0  = m0 + wm + mt * 16 + g;
            float2 v0 = make_float2(acc[mt][nt][0], acc[mt][nt][1]);
            float2 v1 = make_float2(acc[mt][nt][2], acc[mt][nt][3]);
            if (EPI == 3) {
                int kv = col >> 9, h = (col >> 6) & 7, d = col & 63;
                int b0i = r0 >> 11, t0i = r0 & (SEQ - 1);
                int t1i = (r0 + 8) & (SEQ - 1);
                if (kv == 2) {
                    size_t base0 = (((size_t)b0i * NHEADS + h) * DHEAD + d) * SEQ;
                    int et0 = eperm(t0i), et1 = eperm(t1i);
                    __nv_bfloat16 h00 = __float2bfloat16_rn(v0.x);
                    __nv_bfloat16 h01 = __float2bfloat16_rn(v0.y);
                    __nv_bfloat16 h10 = __float2bfloat16_rn(v1.x);
                    __nv_bfloat16 h11 = __float2bfloat16_rn(v1.y);
                    O3h[base0 + et0]       = h00;
                    O3h[base0 + SEQ + et0] = h01;
                    O3h[base0 + et1]       = h10;
                    O3h[base0 + SEQ + et1] = h11;
                    O3l[base0 + et0]       = __float2bfloat16_rn(v0.x - __bfloat162float(h00));
                    O3l[base0 + SEQ + et0] = __float2bfloat16_rn(v0.y - __bfloat162float(h01));
                    O3l[base0 + et1]       = __float2bfloat16_rn(v1.x - __bfloat162float(h10));
                    O3l[base0 + SEQ + et1] = __float2bfloat16_rn(v1.y - __bfloat162float(h11));
                } else {
                    uint32_t* dh = (kv == 0) ? O1h : O2h;
                    uint32_t* dl = (kv == 0) ? O1l : O2l;
                    uint32_t hi0, lo0, hi1, lo1;
                    split2(v0.x, v0.y, hi0, lo0);
                    split2(v1.x, v1.y, hi1, lo1);
                    int dp = pperm(d >> 1);
                    size_t qi0 = (((size_t)b0i * NHEADS + h) * SEQ + t0i) * 32 + dp;
                    size_t qi1 = (((size_t)b0i * NHEADS + h) * SEQ + t1i) * 32 + dp;
                    dh[qi0] = hi0; dl[qi0] = lo0;
                    dh[qi1] = hi1; dl[qi1] = lo1;
                }
            } else if (EPI == 2) {
                float2 bb = *(const float2*)(bias + col);
                v0.x = gelu_exact(v0.x + bb.x); v0.y = gelu_exact(v0.y + bb.y);
                v1.x = gelu_exact(v1.x + bb.x); v1.y = gelu_exact(v1.y + bb.y);
                uint32_t hi0, lo0, hi1, lo1;
                split2(v0.x, v0.y, hi0, lo0);
                split2(v1.x, v1.y, hi1, lo1);
                int cp = pperm(col >> 1);
                size_t oi0 = (size_t)r0 * (N >> 1) + cp;
                size_t oi1 = (size_t)(r0 + 8) * (N >> 1) + cp;
                O1h[oi0] = hi0; O1l[oi0] = lo0;
                O1h[oi1] = hi1; O1l[oi1] = lo1;
            } else {
                if (EPI == 1) {
                    float2 bb = *(const float2*)(bias + col);
                    v0.x += bb.x; v0.y += bb.y;
                    v1.x += bb.x; v1.y += bb.y;
                }
                *(float2*)(C + (size_t)r0 * N + col)       = v0;
                *(float2*)(C + (size_t)(r0 + 8) * N + col) = v1;
            }
        }
    }
}

// ---------------------------------------------------------------------------
// Flash attention, bf16x3 mma.sync, pre-split permuted inputs.
// Smem stride 40 u32 (conflict-free LDS.64).
// ---------------------------------------------------------------------------
#define FSC 40
#define FQH 0
#define FQL 5120
#define FKH 10240
#define FKL 12800
#define FVH 15360
#define FVL 17920
#define FLASH2_SMEM (20480 * 4)

__global__ void __launch_bounds__(256, 2) flash_mma(
    const uint32_t* __restrict__ Qhi, const uint32_t* __restrict__ Qlo,
    const uint32_t* __restrict__ Khi, const uint32_t* __restrict__ Klo,
    const __nv_bfloat16* __restrict__ Vhi, const __nv_bfloat16* __restrict__ Vlo,
    uint32_t* __restrict__ Ohi, uint32_t* __restrict__ Olo)
{
    extern __shared__ uint32_t sm[];
    const int tid  = threadIdx.x;
    const int wid  = tid >> 5;
    const int lane = tid & 31;
    const int g    = lane >> 2;
    const int cq   = lane & 3;
    const int t0   = blockIdx.x * 128;
    const int h    = blockIdx.y;
    const int b    = blockIdx.z;
    const size_t bh = ((size_t)b * NHEADS + h) * SEQ;

    {
        int row = tid >> 1;
        const uint2* qh = (const uint2*)(Qhi + (bh + t0 + row) * 32);
        const uint2* ql = (const uint2*)(Qlo + (bh + t0 + row) * 32);
#pragma unroll
        for (int i = 0; i < 8; i++) {
            int f4 = (tid & 1) + 2 * i;
            uint2 a = qh[f4], bq = ql[f4];
            int di = row * FSC + f4 * 2;
            sm[FQH + di] = a.x;  sm[FQH + di + 1] = a.y;
            sm[FQL + di] = bq.x; sm[FQL + di + 1] = bq.y;
        }
    }

    float o[8][4];
#pragma unroll
    for (int dt = 0; dt < 8; dt++)
#pragma unroll
        for (int e = 0; e < 4; e++) o[dt][e] = 0.0f;
    float m0 = -1e30f, m1 = -1e30f, l0 = 0.0f, l1 = 0.0f;

    const int prow = tid >> 2;
    const __nv_bfloat16* vhrow = Vhi + ((((size_t)b * NHEADS + h) * DHEAD) + prow) * SEQ;
    const __nv_bfloat16* vlrow = Vlo + ((((size_t)b * NHEADS + h) * DHEAD) + prow) * SEQ;
    const int qr = wid * 16 + g;

    for (int jb = 0; jb < SEQ; jb += 64) {
        __syncthreads();
        const uint2* kh2 = (const uint2*)(Khi + (bh + jb + prow) * 32);
        const uint2* kl2 = (const uint2*)(Klo + (bh + jb + prow) * 32);
        const uint2* vh2 = (const uint2*)(vhrow + jb);
        const uint2* vl2 = (const uint2*)(vlrow + jb);
#pragma unroll
        for (int i = 0; i < 4; i++) {
            int f4 = (tid & 3) + i * 4;
            int di = prow * FSC + f4 * 2;
            uint2 a = kh2[f4], c2 = kl2[f4];
            sm[FKH + di] = a.x;  sm[FKH + di + 1] = a.y;
            sm[FKL + di] = c2.x; sm[FKL + di + 1] = c2.y;
            uint2 w = vh2[f4], z2 = vl2[f4];
            sm[FVH + di] = w.x;  sm[FVH + di + 1] = w.y;
            sm[FVL + di] = z2.x; sm[FVL + di + 1] = z2.y;
        }
        __syncthreads();

        // ---- S = Q @ K^T ----
        float s[8][4];
#pragma unroll
        for (int nt = 0; nt < 8; nt++)
#pragma unroll
            for (int e = 0; e < 4; e++) s[nt][e] = 0.0f;

#pragma unroll
        for (int ks = 0; ks < 4; ks++) {
            int qi = qr * FSC + ks * 8 + 2 * cq;
            uint2 q0 = *(const uint2*)&sm[FQH + qi];
            uint2 q1 = *(const uint2*)&sm[FQH + qi + 8 * FSC];
            uint2 r0 = *(const uint2*)&sm[FQL + qi];
            uint2 r1 = *(const uint2*)&sm[FQL + qi + 8 * FSC];
            uint32_t qh[4] = {q0.x, q1.x, q0.y, q1.y};
            uint32_t ql[4] = {r0.x, r1.x, r0.y, r1.y};
            uint32_t kh[8][2], kl[8][2];
#pragma unroll
            for (int nt = 0; nt < 8; nt++) {
                int ki = (nt * 8 + g) * FSC + ks * 8 + 2 * cq;
                uint2 vk = *(const uint2*)&sm[FKH + ki];
                uint2 wk = *(const uint2*)&sm[FKL + ki];
                kh[nt][0] = vk.x; kh[nt][1] = vk.y;
                kl[nt][0] = wk.x; kl[nt][1] = wk.y;
            }
#pragma unroll
            for (int nt = 0; nt < 8; nt++) mma_bf16(s[nt], qh, kh[nt]);
#pragma unroll
            for (int nt = 0; nt < 8; nt++) mma_bf16(s[nt], ql, kh[nt]);
#pragma unroll
            for (int nt = 0; nt < 8; nt++) mma_bf16(s[nt], qh, kl[nt]);
        }

        // ---- online softmax (base 2) ----
        float rm0 = -1e30f, rm1 = -1e30f;
#pragma unroll
        for (int nt = 0; nt < 8; nt++) {
            rm0 = fmaxf(rm0, fmaxf(s[nt][0], s[nt][1]));
            rm1 = fmaxf(rm1, fmaxf(s[nt][2], s[nt][3]));
        }
        rm0 = fmaxf(rm0, __shfl_xor_sync(0xffffffffu, rm0, 1));
        rm0 = fmaxf(rm0, __shfl_xor_sync(0xffffffffu, rm0, 2));
        rm1 = fmaxf(rm1, __shfl_xor_sync(0xffffffffu, rm1, 1));
        rm1 = fmaxf(rm1, __shfl_xor_sync(0xffffffffu, rm1, 2));
        float mn0 = fmaxf(m0, rm0), mn1 = fmaxf(m1, rm1);
        float c0 = exp2f(m0 - mn0), c1 = exp2f(m1 - mn1);
        m0 = mn0; m1 = mn1;
        float rs0 = 0.0f, rs1 = 0.0f;
#pragma unroll
        for (int nt = 0; nt < 8; nt++) {
            s[nt][0] = exp2f(s[nt][0] - mn0);
            s[nt][1] = exp2f(s[nt][1] - mn0);
            s[nt][2] = exp2f(s[nt][2] - mn1);
            s[nt][3] = exp2f(s[nt][3] - mn1);
            rs0 += s[nt][0] + s[nt][1];
            rs1 += s[nt][2] + s[nt][3];
        }
        rs0 += __shfl_xor_sync(0xffffffffu, rs0, 1);
        rs0 += __shfl_xor_sync(0xffffffffu, rs0, 2);
        rs1 += __shfl_xor_sync(0xffffffffu, rs1, 1);
        rs1 += __shfl_xor_sync(0xffffffffu, rs1, 2);
        l0 = l0 * c0 + rs0;
        l1 = l1 * c1 + rs1;
#pragma unroll
        for (int dt = 0; dt < 8; dt++) {
            o[dt][0] *= c0; o[dt][1] *= c0;
            o[dt][2] *= c1; o[dt][3] *= c1;
        }

        // ---- P fragments ----
        uint32_t ph[4][4], pl[4][4];
#pragma unroll
        for (int kj = 0; kj < 4; kj++) {
            split2(s[2*kj][0],   s[2*kj][1],   ph[kj][0], pl[kj][0]);
            split2(s[2*kj][2],   s[2*kj][3],   ph[kj][1], pl[kj][1]);
            split2(s[2*kj+1][0], s[2*kj+1][1], ph[kj][2], pl[kj][2]);
            split2(s[2*kj+1][2], s[2*kj+1][3], ph[kj][3], pl[kj][3]);
        }

        // ---- O += P @ V ----
#pragma unroll
        for (int kj = 0; kj < 4; kj++) {
            uint32_t vh[8][2], vl[8][2];
#pragma unroll
            for (int dt = 0; dt < 8; dt++) {
                int vi = (dt * 8 + g) * FSC + kj * 8 + 2 * cq;
                uint2 a = *(const uint2*)&sm[FVH + vi];
                uint2 c2 = *(const uint2*)&sm[FVL + vi];
                vh[dt][0] = a.x;  vh[dt][1] = a.y;
                vl[dt][0] = c2.x; vl[dt][1] = c2.y;
            }
#pragma unroll
            for (int dt = 0; dt < 8; dt++) mma_bf16(o[dt], ph[kj], vh[dt]);
#pragma unroll
            for (int dt = 0; dt < 8; dt++) mma_bf16(o[dt], pl[kj], vh[dt]);
#pragma unroll
            for (int dt = 0; dt < 8; dt++) mma_bf16(o[dt], ph[kj], vl[dt]);
        }
    }

    // ---- write O (pre-split, permuted) ----
    float inv0 = 1.0f / l0, inv1 = 1.0f / l1;
    int row0 = t0 + wid * 16 + g;
#pragma unroll
    for (int dt = 0; dt < 8; dt++) {
        int col = h * DHEAD + dt * 8 + 2 * cq;
        int cp = pperm(col >> 1);
        uint32_t hi, lo;
        split2(o[dt][0] * inv0, o[dt][1] * inv0, hi, lo);
        size_t oi0 = ((size_t)b * SEQ + row0) * 256 + cp;
        Ohi[oi0] = hi; Olo[oi0] = lo;
        split2(o[dt][2] * inv1, o[dt][3] * inv1, hi, lo);
        size_t oi1 = ((size_t)b * SEQ + row0 + 8) * 256 + cp;
        Ohi[oi1] = hi; Olo[oi1] = lo;
    }
}

// ---------------------------------------------------------------------------
// out = LayerNorm(a + resid) -> fp32 + hi/lo (permuted)
// ---------------------------------------------------------------------------
__global__ void __launch_bounds__(128) add_ln_k(
    const float* __restrict__ A, const float* __restrict__ R,
    const float* __restrict__ g, const float* __restrict__ bb,
    float* __restrict__ out, uint32_t* __restrict__ Ohi, uint32_t* __restrict__ Olo)
{
    __shared__ float red[4];
    int row = blockIdx.x;
    int tid = threadIdx.x;
    int warp = tid >> 5, lane = tid & 31;

    float4 a4 = *(const float4*)(A + (size_t)row * DMODEL + tid * 4);
    float4 r4 = *(const float4*)(R + (size_t)row * DMODEL + tid * 4);
    float x0 = a4.x + r4.x, x1 = a4.y + r4.y, x2 = a4.z + r4.z, x3 = a4.w + r4.w;

    float s = x0 + x1 + x2 + x3;
    s += __shfl_xor_sync(0xffffffffu, s, 16);
    s += __shfl_xor_sync(0xffffffffu, s, 8);
    s += __shfl_xor_sync(0xffffffffu, s, 4);
    s += __shfl_xor_sync(0xffffffffu, s, 2);
    s += __shfl_xor_sync(0xffffffffu, s, 1);
    if (lane == 0) red[warp] = s;
    __syncthreads();
    float mu = (red[0] + red[1] + red[2] + red[3]) * (1.0f / DMODEL);
    __syncthreads();

    float d0 = x0 - mu, d1 = x1 - mu, d2 = x2 - mu, d3 = x3 - mu;
    float s2 = d0*d0 + d1*d1 + d2*d2 + d3*d3;
    s2 += __shfl_xor_sync(0xffffffffu, s2, 16);
    s2 += __shfl_xor_sync(0xffffffffu, s2, 8);
    s2 += __shfl_xor_sync(0xffffffffu, s2, 4);
    s2 += __shfl_xor_sync(0xffffffffu, s2, 2);
    s2 += __shfl_xor_sync(0xffffffffu, s2, 1);
    if (lane == 0) red[warp] = s2;
    __syncthreads();
    float var = (red[0] + red[1] + red[2] + red[3]) * (1.0f / DMODEL);
    float rstd = rsqrtf(var + 1e-5f);

    float4 gv = *(const float4*)(g  + tid * 4);
    float4 bv = *(const float4*)(bb + tid * 4);
    float4 ov = make_float4(d0 * rstd * gv.x + bv.x,
                            d1 * rstd * gv.y + bv.y,
                            d2 * rstd * gv.z + bv.z,
                            d3 * rstd * gv.w + bv.w);
    *(float4*)(out + (size_t)row * DMODEL + tid * 4) = ov;
    uint32_t h0, l0, h1, l1;
    split2(ov.x, ov.y, h0, l0);
    split2(ov.z, ov.w, h1, l1);
    int p0 = tid * 2;
    size_t rb = (size_t)row * 256;
    Ohi[rb + pperm(p0)]     = h0; Olo[rb + pperm(p0)]     = l0;
    Ohi[rb + pperm(p0 + 1)] = h1; Olo[rb + pperm(p0 + 1)] = l1;
}

// ---------------------------------------------------------------------------
// Head
// ---------------------------------------------------------------------------
__global__ void head_k(const float* __restrict__ H, const float* __restrict__ W,
                       const float* __restrict__ bh, float* __restrict__ out)
{
    int gw   = (blockIdx.x * blockDim.x + threadIdx.x) >> 5;
    int lane = threadIdx.x & 31;
    const float* r = H + (size_t)gw * DMODEL;
    float s = 0.0f;
#pragma unroll
    for (int k = 0; k < DMODEL / 32; k++)
        s = fmaf(r[lane + k * 32], W[lane + k * 32], s);
    s += __shfl_xor_sync(0xffffffffu, s, 16);
    s += __shfl_xor_sync(0xffffffffu, s, 8);
    s += __shfl_xor_sync(0xffffffffu, s, 4);
    s += __shfl_xor_sync(0xffffffffu, s, 2);
    s += __shfl_xor_sync(0xffffffffu, s, 1);
    if (lane == 0) out[gw] = s + bh[0];
}

// ---------------------------------------------------------------------------
// Launcher
// ---------------------------------------------------------------------------
extern "C" void kernel_launch(void* const* d_in, const int* in_sizes, int n_in,
                              void* d_out, int out_size)
{
    const int*   x     = (const int*)  d_in[0];
    const float* embed = (const float*)d_in[1];
    const float* pe    = (const float*)d_in[2];
    const float* Wqkv  = (const float*)d_in[3];
    const float* W0    = (const float*)d_in[4];
    const float* g1    = (const float*)d_in[5];
    const float* b1    = (const float*)d_in[6];
    const float* g2    = (const float*)d_in[7];
    const float* b2    = (const float*)d_in[8];
    const float* Wl1   = (const float*)d_in[9];
    const float* bl1   = (const float*)d_in[10];
    const float* Wl2   = (const float*)d_in[11];
    const float* bl2   = (const float*)d_in[12];
    const float* Wh    = (const float*)d_in[13];
    const float* bh    = (const float*)d_in[14];
    float* out = (float*)d_out;

    float *hb, *yb, *ab;
    uint32_t *hhi, *hlo, *yhi, *ylo, *aohi, *aolo, *midhi, *midlo;
    uint32_t *qhi, *qlo, *khi, *klo;
    __nv_bfloat16 *vhi, *vlo;
    uint32_t *wqh, *wql, *w0h, *w0l, *l1h, *l1l, *l2h, *l2l;
    cudaGetSymbolAddress((void**)&hb,    g_h);
    cudaGetSymbolAddress((void**)&yb,    g_y);
    cudaGetSymbolAddress((void**)&ab,    g_a);
    cudaGetSymbolAddress((void**)&hhi,   g_hhi);  cudaGetSymbolAddress((void**)&hlo,   g_hlo);
    cudaGetSymbolAddress((void**)&yhi,   g_yhi);  cudaGetSymbolAddress((void**)&ylo,   g_ylo);
    cudaGetSymbolAddress((void**)&aohi,  g_aohi); cudaGetSymbolAddress((void**)&aolo,  g_aolo);
    cudaGetSymbolAddress((void**)&midhi, g_midhi);cudaGetSymbolAddress((void**)&midlo, g_midlo);
    cudaGetSymbolAddress((void**)&qhi,   g_qhi);  cudaGetSymbolAddress((void**)&qlo,   g_qlo);
    cudaGetSymbolAddress((void**)&khi,   g_khi);  cudaGetSymbolAddress((void**)&klo,   g_klo);
    cudaGetSymbolAddress((void**)&vhi,   g_vhi);  cudaGetSymbolAddress((void**)&vlo,   g_vlo);
    cudaGetSymbolAddress((void**)&wqh,   g_wqkv_hi); cudaGetSymbolAddress((void**)&wql, g_wqkv_lo);
    cudaGetSymbolAddress((void**)&w0h,   g_w0_hi);   cudaGetSymbolAddress((void**)&w0l, g_w0_lo);
    cudaGetSymbolAddress((void**)&l1h,   g_l1_hi);   cudaGetSymbolAddress((void**)&l1l, g_l1_lo);
    cudaGetSymbolAddress((void**)&l2h,   g_l2_hi);   cudaGetSymbolAddress((void**)&l2l, g_l2_lo);

    cudaFuncSetAttribute(flash_mma, cudaFuncAttributeMaxDynamicSharedMemorySize, FLASH2_SMEM);
    cudaFuncSetAttribute(gemm_mma<0>, cudaFuncAttributeMaxDynamicSharedMemorySize, GMM_SMEM);
    cudaFuncSetAttribute(gemm_mma<1>, cudaFuncAttributeMaxDynamicSharedMemorySize, GMM_SMEM);
    cudaFuncSetAttribute(gemm_mma<2>, cudaFuncAttributeMaxDynamicSharedMemorySize, GMM_SMEM);
    cudaFuncSetAttribute(gemm_mma<3>, cudaFuncAttributeMaxDynamicSharedMemorySize, GMM_SMEM);

    wqkvtrans_k<<<dim3((1536 * 256) / 256, NBLOCKS), 256>>>(Wqkv, wqh, wql);
    wtrans_k<<<dim3(16, 16, NBLOCKS), dim3(32, 8)>>>(W0,  w0h, w0l, DMODEL, DMODEL);
    wtrans_k<<<dim3(64, 16, NBLOCKS), dim3(32, 8)>>>(Wl1, l1h, l1l, DMODEL, DFF);
    wtrans_k<<<dim3(16, 64, NBLOCKS), dim3(32, 8)>>>(Wl2, l2h, l2l, DFF, DMODEL);

    embed_k<<<(NROWS * (DMODEL / 4)) / 256, 256>>>(x, embed, pe, hb, hhi, hlo);

    for (int i = 0; i < NBLOCKS; i++) {
        gemm_mma<3><<<dim3(12, 64), 256, GMM_SMEM>>>(
            hhi, hlo, wqh + (size_t)i * 1536 * 256, wql + (size_t)i * 1536 * 256,
            nullptr, nullptr, qhi, qlo, khi, klo, vhi, vlo,
            NROWS, 3 * DMODEL, DMODEL);

        flash_mma<<<dim3(SEQ / 128, NHEADS, BATCH), 256, FLASH2_SMEM>>>(
            qhi, qlo, khi, klo, vhi, vlo, aohi, aolo);

        gemm_mma<0><<<dim3(4, 64), 256, GMM_SMEM>>>(
            aohi, aolo, w0h + (size_t)i * 512 * 256, w0l + (size_t)i * 512 * 256,
            nullptr, ab, nullptr, nullptr, nullptr, nullptr, nullptr, nullptr,
            NROWS, DMODEL, DMODEL);

        add_ln_k<<<NROWS, 128>>>(ab, hb, g1 + i * DMODEL, b1 + i * DMODEL, yb, yhi, ylo);

        gemm_mma<2><<<dim3(16, 64), 256, GMM_SMEM>>>(
            yhi, ylo, l1h + (size_t)i * 2048 * 256, l1l + (size_t)i * 2048 * 256,
            bl1 + i * DFF, nullptr, midhi, midlo, nullptr, nullptr, nullptr, nullptr,
            NROWS, DFF, DMODEL);

        gemm_mma<1><<<dim3(4, 64), 256, GMM_SMEM>>>(
            midhi, midlo, l2h + (size_t)i * 512 * 1024, l2l + (size_t)i * 512 * 1024,
            bl2 + i * DMODEL, ab, nullptr, nullptr, nullptr, nullptr, nullptr, nullptr,
            NROWS, DMODEL, DFF);

        add_ln_k<<<NROWS, 128>>>(ab, yb, g2 + i * DMODEL, b2 + i * DMODEL, hb, hhi, hlo);
    }

    head_k<<<NROWS / 8, 256>>>(hb, Wh, bh, out);
}

// round 11
// speedup vs baseline: 1.0123x; 1.0123x over previous
#include <cuda_runtime.h>
#include <cuda_bf16.h>
#include <cstdint>
#include <math.h>

#define BATCH  4
#define SEQ    2048
#define DMODEL 512
#define NHEADS 8
#define DHEAD  64
#define DFF    2048
#define NBLOCKS 6
#define NROWS  (BATCH * SEQ)

// ---------------------------------------------------------------------------
// Scratch.  bf16-pair arrays stored K-PAIR-PERMUTED: within each 16-pair
// chunk, pair j sits at (j&8)|((j&3)<<1)|((j>>2)&1).
// ---------------------------------------------------------------------------
__device__ float    g_h  [NROWS * DMODEL];
__device__ float    g_y  [NROWS * DMODEL];
__device__ float    g_a  [NROWS * DMODEL];
__device__ uint32_t g_hhi [NROWS * 256],  g_hlo [NROWS * 256];
__device__ uint32_t g_yhi [NROWS * 256],  g_ylo [NROWS * 256];
__device__ uint32_t g_aohi[NROWS * 256],  g_aolo[NROWS * 256];
__device__ uint32_t g_midhi[NROWS * 1024], g_midlo[NROWS * 1024];
__device__ uint32_t g_qhi[BATCH*NHEADS*SEQ*32], g_qlo[BATCH*NHEADS*SEQ*32];
__device__ uint32_t g_khi[BATCH*NHEADS*SEQ*32], g_klo[BATCH*NHEADS*SEQ*32];
__device__ __nv_bfloat16 g_vhi[BATCH*NHEADS*DHEAD*SEQ], g_vlo[BATCH*NHEADS*DHEAD*SEQ];
__device__ uint32_t g_wqkv_hi[NBLOCKS*1536*256], g_wqkv_lo[NBLOCKS*1536*256];
__device__ uint32_t g_w0_hi [NBLOCKS*512*256],  g_w0_lo [NBLOCKS*512*256];
__device__ uint32_t g_l1_hi [NBLOCKS*2048*256], g_l1_lo [NBLOCKS*2048*256];
__device__ uint32_t g_l2_hi [NBLOCKS*512*1024], g_l2_lo [NBLOCKS*512*1024];

__device__ __forceinline__ int pperm(int jg) {
    int j = jg & 15;
    return (jg & ~15) | (j & 8) | ((j & 3) << 1) | ((j >> 2) & 1);
}
__device__ __forceinline__ int eperm(int t) {
    return 2 * pperm(t >> 1) + (t & 1);
}

__device__ __forceinline__ float gelu_exact(float x) {
    return 0.5f * x * (1.0f + erff(x * 0.70710678118654752f));
}

__device__ __forceinline__ void split2(float x, float y, uint32_t& hi, uint32_t& lo) {
    __nv_bfloat16 hx = __float2bfloat16_rn(x);
    __nv_bfloat16 hy = __float2bfloat16_rn(y);
    float rx = x - __bfloat162float(hx);
    float ry = y - __bfloat162float(hy);
    __nv_bfloat162 H; H.x = hx; H.y = hy;
    __nv_bfloat162 L = __floats2bfloat162_rn(rx, ry);
    hi = *reinterpret_cast<uint32_t*>(&H);
    lo = *reinterpret_cast<uint32_t*>(&L);
}

__device__ __forceinline__ void mma_bf16(float* c, const uint32_t* a, const uint32_t* b) {
    asm volatile(
        "mma.sync.aligned.m16n8k16.row.col.f32.bf16.bf16.f32 "
        "{%0,%1,%2,%3}, {%4,%5,%6,%7}, {%8,%9}, {%0,%1,%2,%3};"
        : "+f"(c[0]), "+f"(c[1]), "+f"(c[2]), "+f"(c[3])
        : "r"(a[0]), "r"(a[1]), "r"(a[2]), "r"(a[3]), "r"(b[0]), "r"(b[1]));
}

// ---------------------------------------------------------------------------
// Embedding + PE
// ---------------------------------------------------------------------------
__global__ void embed_k(const int* __restrict__ x, const float* __restrict__ E,
                        const float* __restrict__ pe, float* __restrict__ H,
                        uint32_t* __restrict__ Hhi, uint32_t* __restrict__ Hlo) {
    int idx = blockIdx.x * blockDim.x + threadIdx.x;
    int row = idx >> 7;
    int c   = (idx & 127) << 2;
    int t   = row & (SEQ - 1);
    int tok = x[row];
    float4 e = *(const float4*)(E  + (size_t)tok * DMODEL + c);
    float4 p = *(const float4*)(pe + (size_t)t   * DMODEL + c);
    float4 o = make_float4(e.x + p.x, e.y + p.y, e.z + p.z, e.w + p.w);
    *(float4*)(H + (size_t)row * DMODEL + c) = o;
    uint32_t h0, l0, h1, l1;
    split2(o.x, o.y, h0, l0);
    split2(o.z, o.w, h1, l1);
    int p0 = c >> 1;
    size_t rb = (size_t)row * 256;
    Hhi[rb + pperm(p0)]     = h0; Hlo[rb + pperm(p0)]     = l0;
    Hhi[rb + pperm(p0 + 1)] = h1; Hlo[rb + pperm(p0 + 1)] = l1;
}

// ---------------------------------------------------------------------------
// Weight transpose + split (permuted output)
// ---------------------------------------------------------------------------
__global__ void wtrans_k(const float* __restrict__ W, uint32_t* __restrict__ Whi,
                         uint32_t* __restrict__ Wlo, int K, int N) {
    __shared__ float t[32][33];
    int n0 = blockIdx.x * 32, k0 = blockIdx.y * 32;
    const float* Wz = W + (size_t)blockIdx.z * K * N;
    uint32_t* Whiz = Whi + (size_t)blockIdx.z * N * (K >> 1);
    uint32_t* Wloz = Wlo + (size_t)blockIdx.z * N * (K >> 1);
    int tx = threadIdx.x, ty = threadIdx.y;
    int tid = ty * 32 + tx;
#pragma unroll
    for (int i = 0; i < 32; i += 8)
        t[ty + i][tx] = Wz[(size_t)(k0 + ty + i) * N + n0 + tx];
    __syncthreads();
    int kp = tid & 15, nn = tid >> 4;
    int kpp = (kp & 8) | ((kp & 3) << 1) | ((kp >> 2) & 1);
#pragma unroll
    for (int j = 0; j < 2; j++) {
        int n = nn + 16 * j;
        uint32_t hi, lo;
        split2(t[2 * kp][n], t[2 * kp + 1][n], hi, lo);
        size_t oi = (size_t)(n0 + n) * (K >> 1) + (k0 >> 1) + kpp;
        Whiz[oi] = hi;
        Wloz[oi] = lo;
    }
}

// QKV weight: permuted column n' = kv*512+h*64+d; Q pre-scaled; pair-permuted.
__global__ void wqkvtrans_k(const float* __restrict__ W,
                            uint32_t* __restrict__ Whi, uint32_t* __restrict__ Wlo) {
    int z   = blockIdx.y;
    int idx = blockIdx.x * 256 + threadIdx.x;
    int k2  = idx & 255;
    int np  = idx >> 8;
    int kv  = np >> 9, h = (np >> 6) & 7, d = np & 63;
    int n   = d * 24 + kv * 8 + h;
    const float* Wz = W + (size_t)z * 512 * 1536;
    float x0 = Wz[(size_t)(2 * k2) * 1536 + n];
    float x1 = Wz[(size_t)(2 * k2 + 1) * 1536 + n];
    if (kv == 0) { x0 *= 0.18033688011112042f; x1 *= 0.18033688011112042f; }
    uint32_t hi, lo;
    split2(x0, x1, hi, lo);
    size_t oi = (size_t)z * 1536 * 256 + (size_t)np * 256 + pperm(k2);
    Whi[oi] = hi;
    Wlo[oi] = lo;
}

// ---------------------------------------------------------------------------
// bf16x3 warp-MMA GEMM.  CTA 128x128, 8 warps (64x32), K-chunk 32.
// Round-5 schedule (reg prefetch -> STS -> ONE sync -> compute), pre-split
// inputs, XOR-swizzled unpadded smem (16 u32/row, unit ^= row&3):
// STS.128 and LDS.64 both conflict-free.  2 stages x 32KB = 64KB smem.
// EPI: 0 plain->C, 1 +bias->C, 2 +bias+gelu->hi/lo, 3 QKV scatter
// ---------------------------------------------------------------------------
#define GTILE 2048                     // u32 per tile (128 rows x 16)
#define GSTAGE (4 * GTILE)             // 8192 u32
#define GMM_SMEM (2 * GSTAGE * 4)      // 65536 B

template <int EPI>
__global__ void __launch_bounds__(256) gemm_mma(
    const uint32_t* __restrict__ Ahi, const uint32_t* __restrict__ Alo,
    const uint32_t* __restrict__ Bhi, const uint32_t* __restrict__ Blo,
    const float* __restrict__ bias, float* __restrict__ C,
    uint32_t* __restrict__ O1h, uint32_t* __restrict__ O1l,
    uint32_t* __restrict__ O2h, uint32_t* __restrict__ O2l,
    __nv_bfloat16* __restrict__ O3h, __nv_bfloat16* __restrict__ O3l,
    int M, int N, int K)
{
    extern __shared__ uint32_t sm[];

    const int tid  = threadIdx.x;
    const int wid  = tid >> 5;
    const int lane = tid & 31;
    const int g    = lane >> 2;
    const int cq   = lane & 3;
    const int wm   = (wid & 1) * 64;
    const int wn   = (wid >> 1) * 32;
    const int m0   = blockIdx.y * 128;
    const int n0   = blockIdx.x * 128;
    const int K2   = K >> 1;
    const int NC   = K >> 5;

    const int pu = tid & 3;             // uint4 unit within 16-u32 row
    const int pr = tid >> 2;            // row 0..63 (+64)

    // global row bases for the producer (uint4 view)
    const uint32_t* gbase[4] = {
        Ahi + (size_t)m0 * K2, Alo + (size_t)m0 * K2,
        Bhi + (size_t)n0 * K2, Blo + (size_t)n0 * K2 };

    float acc[4][4][4];
#pragma unroll
    for (int mt = 0; mt < 4; mt++)
#pragma unroll
        for (int nt = 0; nt < 4; nt++)
#pragma unroll
            for (int e = 0; e < 4; e++) acc[mt][nt][e] = 0.0f;

    uint4 pf[8];
    // prefetch chunk 0
#pragma unroll
    for (int t = 0; t < 4; t++) {
#pragma unroll
        for (int hlf = 0; hlf < 2; hlf++) {
            int r = pr + hlf * 64;
            pf[t * 2 + hlf] = *(const uint4*)(gbase[t] + (size_t)r * K2 + pu * 4);
        }
    }

    // precomputed swizzled STS targets
    uint32_t sts_off[8];
#pragma unroll
    for (int t = 0; t < 4; t++)
#pragma unroll
        for (int hlf = 0; hlf < 2; hlf++) {
            int r = pr + hlf * 64;
            sts_off[t * 2 + hlf] = t * GTILE + r * 16 + ((pu ^ (r & 3)) << 2);
        }

    for (int c = 0; c < NC; c++) {
        uint32_t* sp = sm + (c & 1) * GSTAGE;
        // store prefetched chunk
#pragma unroll
        for (int i = 0; i < 8; i++)
            *(uint4*)(sp + sts_off[i]) = pf[i];
        __syncthreads();

        // prefetch next chunk
        if (c + 1 < NC) {
            const int k4 = (c + 1) << 4;
#pragma unroll
            for (int t = 0; t < 4; t++)
#pragma unroll
                for (int hlf = 0; hlf < 2; hlf++) {
                    int r = pr + hlf * 64;
                    pf[t * 2 + hlf] =
                        *(const uint4*)(gbase[t] + (size_t)r * K2 + k4 + pu * 4);
                }
        }

        // compute chunk (2 k16 slices)
#pragma unroll
        for (int ks = 0; ks < 2; ks++) {
            const int lu  = ks * 2 + (cq >> 1);   // logical uint4 unit
            const int off = (2 * cq) & 3;         // u32 offset inside unit
            uint32_t bh[4][2], bl[4][2];
#pragma unroll
            for (int nt = 0; nt < 4; nt++) {
                int r = wn + nt * 8 + g;
                int w = r * 16 + ((lu ^ (r & 3)) << 2) + off;
                uint2 vbh = *(const uint2*)&sp[2 * GTILE + w];
                uint2 vbl = *(const uint2*)&sp[3 * GTILE + w];
                bh[nt][0] = vbh.x; bh[nt][1] = vbh.y;
                bl[nt][0] = vbl.x; bl[nt][1] = vbl.y;
            }
#pragma unroll
            for (int mt = 0; mt < 4; mt++) {
                int r0i = wm + mt * 16 + g;
                int r1i = r0i + 8;
                int w0 = r0i * 16 + ((lu ^ (r0i & 3)) << 2) + off;
                int w1 = r1i * 16 + ((lu ^ (r1i & 3)) << 2) + off;
                uint2 a0 = *(const uint2*)&sp[w0];
                uint2 a1 = *(const uint2*)&sp[w1];
                uint2 c0 = *(const uint2*)&sp[GTILE + w0];
                uint2 c1 = *(const uint2*)&sp[GTILE + w1];
                uint32_t ah[4] = {a0.x, a1.x, a0.y, a1.y};
                uint32_t al[4] = {c0.x, c1.x, c0.y, c1.y};
#pragma unroll
                for (int nt = 0; nt < 4; nt++) mma_bf16(acc[mt][nt], ah, bh[nt]);
#pragma unroll
                for (int nt = 0; nt < 4; nt++) mma_bf16(acc[mt][nt], al, bh[nt]);
#pragma unroll
                for (int nt = 0; nt < 4; nt++) mma_bf16(acc[mt][nt], ah, bl[nt]);
            }
        }
        // single sync per chunk: stage reuse separated by next iteration's sync
    }

    // ---- epilogue ----
#pragma unroll
    for (int mt = 0; mt < 4; mt++) {
#pragma unroll
        for (int nt = 0; nt < 4; nt++) {
            int col = n0 + wn + nt * 8 + 2 * cq;
            int r0  = m0 + wm + mt * 16 + g;
            float2 v0 = make_float2(acc[mt][nt][0], acc[mt][nt][1]);
            float2 v1 = make_float2(acc[mt][nt][2], acc[mt][nt][3]);
            if (EPI == 3) {
                int kv = col >> 9, h = (col >> 6) & 7, d = col & 63;
                int b0i = r0 >> 11, t0i = r0 & (SEQ - 1);
                int t1i = (r0 + 8) & (SEQ - 1);
                if (kv == 2) {
                    size_t base0 = (((size_t)b0i * NHEADS + h) * DHEAD + d) * SEQ;
                    int et0 = eperm(t0i), et1 = eperm(t1i);
                    __nv_bfloat16 h00 = __float2bfloat16_rn(v0.x);
                    __nv_bfloat16 h01 = __float2bfloat16_rn(v0.y);
                    __nv_bfloat16 h10 = __float2bfloat16_rn(v1.x);
                    __nv_bfloat16 h11 = __float2bfloat16_rn(v1.y);
                    O3h[base0 + et0]       = h00;
                    O3h[base0 + SEQ + et0] = h01;
                    O3h[base0 + et1]       = h10;
                    O3h[base0 + SEQ + et1] = h11;
                    O3l[base0 + et0]       = __float2bfloat16_rn(v0.x - __bfloat162float(h00));
                    O3l[base0 + SEQ + et0] = __float2bfloat16_rn(v0.y - __bfloat162float(h01));
                    O3l[base0 + et1]       = __float2bfloat16_rn(v1.x - __bfloat162float(h10));
                    O3l[base0 + SEQ + et1] = __float2bfloat16_rn(v1.y - __bfloat162float(h11));
                } else {
                    uint32_t* dh = (kv == 0) ? O1h : O2h;
                    uint32_t* dl = (kv == 0) ? O1l : O2l;
                    uint32_t hi0, lo0, hi1, lo1;
                    split2(v0.x, v0.y, hi0, lo0);
                    split2(v1.x, v1.y, hi1, lo1);
                    int dp = pperm(d >> 1);
                    size_t qi0 = (((size_t)b0i * NHEADS + h) * SEQ + t0i) * 32 + dp;
                    size_t qi1 = (((size_t)b0i * NHEADS + h) * SEQ + t1i) * 32 + dp;
                    dh[qi0] = hi0; dl[qi0] = lo0;
                    dh[qi1] = hi1; dl[qi1] = lo1;
                }
            } else if (EPI == 2) {
                float2 bb = *(const float2*)(bias + col);
                v0.x = gelu_exact(v0.x + bb.x); v0.y = gelu_exact(v0.y + bb.y);
                v1.x = gelu_exact(v1.x + bb.x); v1.y = gelu_exact(v1.y + bb.y);
                uint32_t hi0, lo0, hi1, lo1;
                split2(v0.x, v0.y, hi0, lo0);
                split2(v1.x, v1.y, hi1, lo1);
                int cp = pperm(col >> 1);
                size_t oi0 = (size_t)r0 * (N >> 1) + cp;
                size_t oi1 = (size_t)(r0 + 8) * (N >> 1) + cp;
                O1h[oi0] = hi0; O1l[oi0] = lo0;
                O1h[oi1] = hi1; O1l[oi1] = lo1;
            } else {
                if (EPI == 1) {
                    float2 bb = *(const float2*)(bias + col);
                    v0.x += bb.x; v0.y += bb.y;
                    v1.x += bb.x; v1.y += bb.y;
                }
                *(float2*)(C + (size_t)r0 * N + col)       = v0;
                *(float2*)(C + (size_t)(r0 + 8) * N + col) = v1;
            }
        }
    }
}

// ---------------------------------------------------------------------------
// Flash attention, bf16x3 mma.sync, pre-split permuted inputs.
// Smem stride 40 u32 (conflict-free LDS.64).
// ---------------------------------------------------------------------------
#define FSC 40
#define FQH 0
#define FQL 5120
#define FKH 10240
#define FKL 12800
#define FVH 15360
#define FVL 17920
#define FLASH2_SMEM (20480 * 4)

__global__ void __launch_bounds__(256, 2) flash_mma(
    const uint32_t* __restrict__ Qhi, const uint32_t* __restrict__ Qlo,
    const uint32_t* __restrict__ Khi, const uint32_t* __restrict__ Klo,
    const __nv_bfloat16* __restrict__ Vhi, const __nv_bfloat16* __restrict__ Vlo,
    uint32_t* __restrict__ Ohi, uint32_t* __restrict__ Olo)
{
    extern __shared__ uint32_t sm[];
    const int tid  = threadIdx.x;
    const int wid  = tid >> 5;
    const int lane = tid & 31;
    const int g    = lane >> 2;
    const int cq   = lane & 3;
    const int t0   = blockIdx.x * 128;
    const int h    = blockIdx.y;
    const int b    = blockIdx.z;
    const size_t bh = ((size_t)b * NHEADS + h) * SEQ;

    {
        int row = tid >> 1;
        const uint2* qh = (const uint2*)(Qhi + (bh + t0 + row) * 32);
        const uint2* ql = (const uint2*)(Qlo + (bh + t0 + row) * 32);
#pragma unroll
        for (int i = 0; i < 8; i++) {
            int f4 = (tid & 1) + 2 * i;
            uint2 a = qh[f4], bq = ql[f4];
            int di = row * FSC + f4 * 2;
            sm[FQH + di] = a.x;  sm[FQH + di + 1] = a.y;
            sm[FQL + di] = bq.x; sm[FQL + di + 1] = bq.y;
        }
    }

    float o[8][4];
#pragma unroll
    for (int dt = 0; dt < 8; dt++)
#pragma unroll
        for (int e = 0; e < 4; e++) o[dt][e] = 0.0f;
    float m0 = -1e30f, m1 = -1e30f, l0 = 0.0f, l1 = 0.0f;

    const int prow = tid >> 2;
    const __nv_bfloat16* vhrow = Vhi + ((((size_t)b * NHEADS + h) * DHEAD) + prow) * SEQ;
    const __nv_bfloat16* vlrow = Vlo + ((((size_t)b * NHEADS + h) * DHEAD) + prow) * SEQ;
    const int qr = wid * 16 + g;

    for (int jb = 0; jb < SEQ; jb += 64) {
        __syncthreads();
        const uint2* kh2 = (const uint2*)(Khi + (bh + jb + prow) * 32);
        const uint2* kl2 = (const uint2*)(Klo + (bh + jb + prow) * 32);
        const uint2* vh2 = (const uint2*)(vhrow + jb);
        const uint2* vl2 = (const uint2*)(vlrow + jb);
#pragma unroll
        for (int i = 0; i < 4; i++) {
            int f4 = (tid & 3) + i * 4;
            int di = prow * FSC + f4 * 2;
            uint2 a = kh2[f4], c2 = kl2[f4];
            sm[FKH + di] = a.x;  sm[FKH + di + 1] = a.y;
            sm[FKL + di] = c2.x; sm[FKL + di + 1] = c2.y;
            uint2 w = vh2[f4], z2 = vl2[f4];
            sm[FVH + di] = w.x;  sm[FVH + di + 1] = w.y;
            sm[FVL + di] = z2.x; sm[FVL + di + 1] = z2.y;
        }
        __syncthreads();

        float s[8][4];
#pragma unroll
        for (int nt = 0; nt < 8; nt++)
#pragma unroll
            for (int e = 0; e < 4; e++) s[nt][e] = 0.0f;

#pragma unroll
        for (int ks = 0; ks < 4; ks++) {
            int qi = qr * FSC + ks * 8 + 2 * cq;
            uint2 q0 = *(const uint2*)&sm[FQH + qi];
            uint2 q1 = *(const uint2*)&sm[FQH + qi + 8 * FSC];
            uint2 r0 = *(const uint2*)&sm[FQL + qi];
            uint2 r1 = *(const uint2*)&sm[FQL + qi + 8 * FSC];
            uint32_t qh[4] = {q0.x, q1.x, q0.y, q1.y};
            uint32_t ql[4] = {r0.x, r1.x, r0.y, r1.y};
            uint32_t kh[8][2], kl[8][2];
#pragma unroll
            for (int nt = 0; nt < 8; nt++) {
                int ki = (nt * 8 + g) * FSC + ks * 8 + 2 * cq;
                uint2 vk = *(const uint2*)&sm[FKH + ki];
                uint2 wk = *(const uint2*)&sm[FKL + ki];
                kh[nt][0] = vk.x; kh[nt][1] = vk.y;
                kl[nt][0] = wk.x; kl[nt][1] = wk.y;
            }
#pragma unroll
            for (int nt = 0; nt < 8; nt++) mma_bf16(s[nt], qh, kh[nt]);
#pragma unroll
            for (int nt = 0; nt < 8; nt++) mma_bf16(s[nt], ql, kh[nt]);
#pragma unroll
            for (int nt = 0; nt < 8; nt++) mma_bf16(s[nt], qh, kl[nt]);
        }

        float rm0 = -1e30f, rm1 = -1e30f;
#pragma unroll
        for (int nt = 0; nt < 8; nt++) {
            rm0 = fmaxf(rm0, fmaxf(s[nt][0], s[nt][1]));
            rm1 = fmaxf(rm1, fmaxf(s[nt][2], s[nt][3]));
        }
        rm0 = fmaxf(rm0, __shfl_xor_sync(0xffffffffu, rm0, 1));
        rm0 = fmaxf(rm0, __shfl_xor_sync(0xffffffffu, rm0, 2));
        rm1 = fmaxf(rm1, __shfl_xor_sync(0xffffffffu, rm1, 1));
        rm1 = fmaxf(rm1, __shfl_xor_sync(0xffffffffu, rm1, 2));
        float mn0 = fmaxf(m0, rm0), mn1 = fmaxf(m1, rm1);
        float c0 = exp2f(m0 - mn0), c1 = exp2f(m1 - mn1);
        m0 = mn0; m1 = mn1;
        float rs0 = 0.0f, rs1 = 0.0f;
#pragma unroll
        for (int nt = 0; nt < 8; nt++) {
            s[nt][0] = exp2f(s[nt][0] - mn0);
            s[nt][1] = exp2f(s[nt][1] - mn0);
            s[nt][2] = exp2f(s[nt][2] - mn1);
            s[nt][3] = exp2f(s[nt][3] - mn1);
            rs0 += s[nt][0] + s[nt][1];
            rs1 += s[nt][2] + s[nt][3];
        }
        rs0 += __shfl_xor_sync(0xffffffffu, rs0, 1);
        rs0 += __shfl_xor_sync(0xffffffffu, rs0, 2);
        rs1 += __shfl_xor_sync(0xffffffffu, rs1, 1);
        rs1 += __shfl_xor_sync(0xffffffffu, rs1, 2);
        l0 = l0 * c0 + rs0;
        l1 = l1 * c1 + rs1;
#pragma unroll
        for (int dt = 0; dt < 8; dt++) {
            o[dt][0] *= c0; o[dt][1] *= c0;
            o[dt][2] *= c1; o[dt][3] *= c1;
        }

        uint32_t ph[4][4], pl[4][4];
#pragma unroll
        for (int kj = 0; kj < 4; kj++) {
            split2(s[2*kj][0],   s[2*kj][1],   ph[kj][0], pl[kj][0]);
            split2(s[2*kj][2],   s[2*kj][3],   ph[kj][1], pl[kj][1]);
            split2(s[2*kj+1][0], s[2*kj+1][1], ph[kj][2], pl[kj][2]);
            split2(s[2*kj+1][2], s[2*kj+1][3], ph[kj][3], pl[kj][3]);
        }

#pragma unroll
        for (int kj = 0; kj < 4; kj++) {
            uint32_t vh[8][2], vl[8][2];
#pragma unroll
            for (int dt = 0; dt < 8; dt++) {
                int vi = (dt * 8 + g) * FSC + kj * 8 + 2 * cq;
                uint2 a = *(const uint2*)&sm[FVH + vi];
                uint2 c2 = *(const uint2*)&sm[FVL + vi];
                vh[dt][0] = a.x;  vh[dt][1] = a.y;
                vl[dt][0] = c2.x; vl[dt][1] = c2.y;
            }
#pragma unroll
            for (int dt = 0; dt < 8; dt++) mma_bf16(o[dt], ph[kj], vh[dt]);
#pragma unroll
            for (int dt = 0; dt < 8; dt++) mma_bf16(o[dt], pl[kj], vh[dt]);
#pragma unroll
            for (int dt = 0; dt < 8; dt++) mma_bf16(o[dt], ph[kj], vl[dt]);
        }
    }

    float inv0 = 1.0f / l0, inv1 = 1.0f / l1;
    int row0 = t0 + wid * 16 + g;
#pragma unroll
    for (int dt = 0; dt < 8; dt++) {
        int col = h * DHEAD + dt * 8 + 2 * cq;
        int cp = pperm(col >> 1);
        uint32_t hi, lo;
        split2(o[dt][0] * inv0, o[dt][1] * inv0, hi, lo);
        size_t oi0 = ((size_t)b * SEQ + row0) * 256 + cp;
        Ohi[oi0] = hi; Olo[oi0] = lo;
        split2(o[dt][2] * inv1, o[dt][3] * inv1, hi, lo);
        size_t oi1 = ((size_t)b * SEQ + row0 + 8) * 256 + cp;
        Ohi[oi1] = hi; Olo[oi1] = lo;
    }
}

// ---------------------------------------------------------------------------
// out = LayerNorm(a + resid) -> fp32 + hi/lo (permuted)
// ---------------------------------------------------------------------------
__global__ void __launch_bounds__(128) add_ln_k(
    const float* __restrict__ A, const float* __restrict__ R,
    const float* __restrict__ g, const float* __restrict__ bb,
    float* __restrict__ out, uint32_t* __restrict__ Ohi, uint32_t* __restrict__ Olo)
{
    __shared__ float red[4];
    int row = blockIdx.x;
    int tid = threadIdx.x;
    int warp = tid >> 5, lane = tid & 31;

    float4 a4 = *(const float4*)(A + (size_t)row * DMODEL + tid * 4);
    float4 r4 = *(const float4*)(R + (size_t)row * DMODEL + tid * 4);
    float x0 = a4.x + r4.x, x1 = a4.y + r4.y, x2 = a4.z + r4.z, x3 = a4.w + r4.w;

    float s = x0 + x1 + x2 + x3;
    s += __shfl_xor_sync(0xffffffffu, s, 16);
    s += __shfl_xor_sync(0xffffffffu, s, 8);
    s += __shfl_xor_sync(0xffffffffu, s, 4);
    s += __shfl_xor_sync(0xffffffffu, s, 2);
    s += __shfl_xor_sync(0xffffffffu, s, 1);
    if (lane == 0) red[warp] = s;
    __syncthreads();
    float mu = (red[0] + red[1] + red[2] + red[3]) * (1.0f / DMODEL);
    __syncthreads();

    float d0 = x0 - mu, d1 = x1 - mu, d2 = x2 - mu, d3 = x3 - mu;
    float s2 = d0*d0 + d1*d1 + d2*d2 + d3*d3;
    s2 += __shfl_xor_sync(0xffffffffu, s2, 16);
    s2 += __shfl_xor_sync(0xffffffffu, s2, 8);
    s2 += __shfl_xor_sync(0xffffffffu, s2, 4);
    s2 += __shfl_xor_sync(0xffffffffu, s2, 2);
    s2 += __shfl_xor_sync(0xffffffffu, s2, 1);
    if (lane == 0) red[warp] = s2;
    __syncthreads();
    float var = (red[0] + red[1] + red[2] + red[3]) * (1.0f / DMODEL);
    float rstd = rsqrtf(var + 1e-5f);

    float4 gv = *(const float4*)(g  + tid * 4);
    float4 bv = *(const float4*)(bb + tid * 4);
    float4 ov = make_float4(d0 * rstd * gv.x + bv.x,
                            d1 * rstd * gv.y + bv.y,
                            d2 * rstd * gv.z + bv.z,
                            d3 * rstd * gv.w + bv.w);
    *(float4*)(out + (size_t)row * DMODEL + tid * 4) = ov;
    uint32_t h0, l0, h1, l1;
    split2(ov.x, ov.y, h0, l0);
    split2(ov.z, ov.w, h1, l1);
    int p0 = tid * 2;
    size_t rb = (size_t)row * 256;
    Ohi[rb + pperm(p0)]     = h0; Olo[rb + pperm(p0)]     = l0;
    Ohi[rb + pperm(p0 + 1)] = h1; Olo[rb + pperm(p0 + 1)] = l1;
}

// ---------------------------------------------------------------------------
// Head
// ---------------------------------------------------------------------------
__global__ void head_k(const float* __restrict__ H, const float* __restrict__ W,
                       const float* __restrict__ bh, float* __restrict__ out)
{
    int gw   = (blockIdx.x * blockDim.x + threadIdx.x) >> 5;
    int lane = threadIdx.x & 31;
    const float* r = H + (size_t)gw * DMODEL;
    float s = 0.0f;
#pragma unroll
    for (int k = 0; k < DMODEL / 32; k++)
        s = fmaf(r[lane + k * 32], W[lane + k * 32], s);
    s += __shfl_xor_sync(0xffffffffu, s, 16);
    s += __shfl_xor_sync(0xffffffffu, s, 8);
    s += __shfl_xor_sync(0xffffffffu, s, 4);
    s += __shfl_xor_sync(0xffffffffu, s, 2);
    s += __shfl_xor_sync(0xffffffffu, s, 1);
    if (lane == 0) out[gw] = s + bh[0];
}

// ---------------------------------------------------------------------------
// Launcher
// ---------------------------------------------------------------------------
extern "C" void kernel_launch(void* const* d_in, const int* in_sizes, int n_in,
                              void* d_out, int out_size)
{
    const int*   x     = (const int*)  d_in[0];
    const float* embed = (const float*)d_in[1];
    const float* pe    = (const float*)d_in[2];
    const float* Wqkv  = (const float*)d_in[3];
    const float* W0    = (const float*)d_in[4];
    const float* g1    = (const float*)d_in[5];
    const float* b1    = (const float*)d_in[6];
    const float* g2    = (const float*)d_in[7];
    const float* b2    = (const float*)d_in[8];
    const float* Wl1   = (const float*)d_in[9];
    const float* bl1   = (const float*)d_in[10];
    const float* Wl2   = (const float*)d_in[11];
    const float* bl2   = (const float*)d_in[12];
    const float* Wh    = (const float*)d_in[13];
    const float* bh    = (const float*)d_in[14];
    float* out = (float*)d_out;

    float *hb, *yb, *ab;
    uint32_t *hhi, *hlo, *yhi, *ylo, *aohi, *aolo, *midhi, *midlo;
    uint32_t *qhi, *qlo, *khi, *klo;
    __nv_bfloat16 *vhi, *vlo;
    uint32_t *wqh, *wql, *w0h, *w0l, *l1h, *l1l, *l2h, *l2l;
    cudaGetSymbolAddress((void**)&hb,    g_h);
    cudaGetSymbolAddress((void**)&yb,    g_y);
    cudaGetSymbolAddress((void**)&ab,    g_a);
    cudaGetSymbolAddress((void**)&hhi,   g_hhi);  cudaGetSymbolAddress((void**)&hlo,   g_hlo);
    cudaGetSymbolAddress((void**)&yhi,   g_yhi);  cudaGetSymbolAddress((void**)&ylo,   g_ylo);
    cudaGetSymbolAddress((void**)&aohi,  g_aohi); cudaGetSymbolAddress((void**)&aolo,  g_aolo);
    cudaGetSymbolAddress((void**)&midhi, g_midhi);cudaGetSymbolAddress((void**)&midlo, g_midlo);
    cudaGetSymbolAddress((void**)&qhi,   g_qhi);  cudaGetSymbolAddress((void**)&qlo,   g_qlo);
    cudaGetSymbolAddress((void**)&khi,   g_khi);  cudaGetSymbolAddress((void**)&klo,   g_klo);
    cudaGetSymbolAddress((void**)&vhi,   g_vhi);  cudaGetSymbolAddress((void**)&vlo,   g_vlo);
    cudaGetSymbolAddress((void**)&wqh,   g_wqkv_hi); cudaGetSymbolAddress((void**)&wql, g_wqkv_lo);
    cudaGetSymbolAddress((void**)&w0h,   g_w0_hi);   cudaGetSymbolAddress((void**)&w0l, g_w0_lo);
    cudaGetSymbolAddress((void**)&l1h,   g_l1_hi);   cudaGetSymbolAddress((void**)&l1l, g_l1_lo);
    cudaGetSymbolAddress((void**)&l2h,   g_l2_hi);   cudaGetSymbolAddress((void**)&l2l, g_l2_lo);

    cudaFuncSetAttribute(flash_mma, cudaFuncAttributeMaxDynamicSharedMemorySize, FLASH2_SMEM);
    cudaFuncSetAttribute(gemm_mma<0>, cudaFuncAttributeMaxDynamicSharedMemorySize, GMM_SMEM);
    cudaFuncSetAttribute(gemm_mma<1>, cudaFuncAttributeMaxDynamicSharedMemorySize, GMM_SMEM);
    cudaFuncSetAttribute(gemm_mma<2>, cudaFuncAttributeMaxDynamicSharedMemorySize, GMM_SMEM);
    cudaFuncSetAttribute(gemm_mma<3>, cudaFuncAttributeMaxDynamicSharedMemorySize, GMM_SMEM);

    wqkvtrans_k<<<dim3((1536 * 256) / 256, NBLOCKS), 256>>>(Wqkv, wqh, wql);
    wtrans_k<<<dim3(16, 16, NBLOCKS), dim3(32, 8)>>>(W0,  w0h, w0l, DMODEL, DMODEL);
    wtrans_k<<<dim3(64, 16, NBLOCKS), dim3(32, 8)>>>(Wl1, l1h, l1l, DMODEL, DFF);
    wtrans_k<<<dim3(16, 64, NBLOCKS), dim3(32, 8)>>>(Wl2, l2h, l2l, DFF, DMODEL);

    embed_k<<<(NROWS * (DMODEL / 4)) / 256, 256>>>(x, embed, pe, hb, hhi, hlo);

    for (int i = 0; i < NBLOCKS; i++) {
        gemm_mma<3><<<dim3(12, 64), 256, GMM_SMEM>>>(
            hhi, hlo, wqh + (size_t)i * 1536 * 256, wql + (size_t)i * 1536 * 256,
            nullptr, nullptr, qhi, qlo, khi, klo, vhi, vlo,
            NROWS, 3 * DMODEL, DMODEL);

        flash_mma<<<dim3(SEQ / 128, NHEADS, BATCH), 256, FLASH2_SMEM>>>(
            qhi, qlo, khi, klo, vhi, vlo, aohi, aolo);

        gemm_mma<0><<<dim3(4, 64), 256, GMM_SMEM>>>(
            aohi, aolo, w0h + (size_t)i * 512 * 256, w0l + (size_t)i * 512 * 256,
            nullptr, ab, nullptr, nullptr, nullptr, nullptr, nullptr, nullptr,
            NROWS, DMODEL, DMODEL);

        add_ln_k<<<NROWS, 128>>>(ab, hb, g1 + i * DMODEL, b1 + i * DMODEL, yb, yhi, ylo);

        gemm_mma<2><<<dim3(16, 64), 256, GMM_SMEM>>>(
            yhi, ylo, l1h + (size_t)i * 2048 * 256, l1l + (size_t)i * 2048 * 256,
            bl1 + i * DFF, nullptr, midhi, midlo, nullptr, nullptr, nullptr, nullptr,
            NROWS, DFF, DMODEL);

        gemm_mma<1><<<dim3(4, 64), 256, GMM_SMEM>>>(
            midhi, midlo, l2h + (size_t)i * 512 * 1024, l2l + (size_t)i * 512 * 1024,
            bl2 + i * DMODEL, ab, nullptr, nullptr, nullptr, nullptr, nullptr, nullptr,
            NROWS, DMODEL, DFF);

        add_ln_k<<<NROWS, 128>>>(ab, yb, g2 + i * DMODEL, b2 + i * DMODEL, hb, hhi, hlo);
    }

    head_k<<<NROWS / 8, 256>>>(hb, Wh, bh, out);
}

// round 12
// speedup vs baseline: 1.0158x; 1.0034x over previous
#include <cuda_runtime.h>
#include <cuda_bf16.h>
#include <cstdint>
#include <math.h>

#define BATCH  4
#define SEQ    2048
#define DMODEL 512
#define NHEADS 8
#define DHEAD  64
#define DFF    2048
#define NBLOCKS 6
#define NROWS  (BATCH * SEQ)

// ---------------------------------------------------------------------------
// Scratch.  bf16-pair arrays stored K-PAIR-PERMUTED: within each 16-pair
// chunk, pair j sits at (j&8)|((j&3)<<1)|((j>>2)&1).
// ---------------------------------------------------------------------------
__device__ float    g_h  [NROWS * DMODEL];
__device__ float    g_y  [NROWS * DMODEL];
__device__ float    g_a  [NROWS * DMODEL];
__device__ uint32_t g_hhi [NROWS * 256],  g_hlo [NROWS * 256];
__device__ uint32_t g_yhi [NROWS * 256],  g_ylo [NROWS * 256];
__device__ uint32_t g_aohi[NROWS * 256],  g_aolo[NROWS * 256];
__device__ uint32_t g_midhi[NROWS * 1024], g_midlo[NROWS * 1024];
__device__ uint32_t g_qhi[BATCH*NHEADS*SEQ*32], g_qlo[BATCH*NHEADS*SEQ*32];
__device__ uint32_t g_khi[BATCH*NHEADS*SEQ*32], g_klo[BATCH*NHEADS*SEQ*32];
__device__ __nv_bfloat16 g_vhi[BATCH*NHEADS*DHEAD*SEQ], g_vlo[BATCH*NHEADS*DHEAD*SEQ];
__device__ uint32_t g_wqkv_hi[NBLOCKS*1536*256], g_wqkv_lo[NBLOCKS*1536*256];
__device__ uint32_t g_w0_hi [NBLOCKS*512*256],  g_w0_lo [NBLOCKS*512*256];
__device__ uint32_t g_l1_hi [NBLOCKS*2048*256], g_l1_lo [NBLOCKS*2048*256];
__device__ uint32_t g_l2_hi [NBLOCKS*512*1024], g_l2_lo [NBLOCKS*512*1024];

__device__ __forceinline__ int pperm(int jg) {
    int j = jg & 15;
    return (jg & ~15) | (j & 8) | ((j & 3) << 1) | ((j >> 2) & 1);
}
__device__ __forceinline__ int eperm(int t) {
    return 2 * pperm(t >> 1) + (t & 1);
}

__device__ __forceinline__ float gelu_exact(float x) {
    return 0.5f * x * (1.0f + erff(x * 0.70710678118654752f));
}

__device__ __forceinline__ void split2(float x, float y, uint32_t& hi, uint32_t& lo) {
    __nv_bfloat16 hx = __float2bfloat16_rn(x);
    __nv_bfloat16 hy = __float2bfloat16_rn(y);
    float rx = x - __bfloat162float(hx);
    float ry = y - __bfloat162float(hy);
    __nv_bfloat162 H; H.x = hx; H.y = hy;
    __nv_bfloat162 L = __floats2bfloat162_rn(rx, ry);
    hi = *reinterpret_cast<uint32_t*>(&H);
    lo = *reinterpret_cast<uint32_t*>(&L);
}

__device__ __forceinline__ void mma_bf16(float* c, const uint32_t* a, const uint32_t* b) {
    asm volatile(
        "mma.sync.aligned.m16n8k16.row.col.f32.bf16.bf16.f32 "
        "{%0,%1,%2,%3}, {%4,%5,%6,%7}, {%8,%9}, {%0,%1,%2,%3};"
        : "+f"(c[0]), "+f"(c[1]), "+f"(c[2]), "+f"(c[3])
        : "r"(a[0]), "r"(a[1]), "r"(a[2]), "r"(a[3]), "r"(b[0]), "r"(b[1]));
}

__device__ __forceinline__ uint32_t smem_u32(const void* p) {
    uint32_t a;
    asm("{ .reg .u64 t; cvta.to.shared.u64 t, %1; cvt.u32.u64 %0, t; }"
        : "=r"(a) : "l"(p));
    return a;
}
__device__ __forceinline__ void cp16(uint32_t sa, const void* ga) {
    asm volatile("cp.async.ca.shared.global [%0], [%1], 16;" :: "r"(sa), "l"(ga));
}
#define CP_COMMIT() asm volatile("cp.async.commit_group;" ::: "memory")
#define CP_WAIT1()  asm volatile("cp.async.wait_group 1;" ::: "memory")

// ---------------------------------------------------------------------------
// Embedding + PE
// ---------------------------------------------------------------------------
__global__ void embed_k(const int* __restrict__ x, const float* __restrict__ E,
                        const float* __restrict__ pe, float* __restrict__ H,
                        uint32_t* __restrict__ Hhi, uint32_t* __restrict__ Hlo) {
    int idx = blockIdx.x * blockDim.x + threadIdx.x;
    int row = idx >> 7;
    int c   = (idx & 127) << 2;
    int t   = row & (SEQ - 1);
    int tok = x[row];
    float4 e = *(const float4*)(E  + (size_t)tok * DMODEL + c);
    float4 p = *(const float4*)(pe + (size_t)t   * DMODEL + c);
    float4 o = make_float4(e.x + p.x, e.y + p.y, e.z + p.z, e.w + p.w);
    *(float4*)(H + (size_t)row * DMODEL + c) = o;
    uint32_t h0, l0, h1, l1;
    split2(o.x, o.y, h0, l0);
    split2(o.z, o.w, h1, l1);
    int p0 = c >> 1;
    size_t rb = (size_t)row * 256;
    Hhi[rb + pperm(p0)]     = h0; Hlo[rb + pperm(p0)]     = l0;
    Hhi[rb + pperm(p0 + 1)] = h1; Hlo[rb + pperm(p0 + 1)] = l1;
}

// ---------------------------------------------------------------------------
// Weight transpose + split (permuted output)
// ---------------------------------------------------------------------------
__global__ void wtrans_k(const float* __restrict__ W, uint32_t* __restrict__ Whi,
                         uint32_t* __restrict__ Wlo, int K, int N) {
    __shared__ float t[32][33];
    int n0 = blockIdx.x * 32, k0 = blockIdx.y * 32;
    const float* Wz = W + (size_t)blockIdx.z * K * N;
    uint32_t* Whiz = Whi + (size_t)blockIdx.z * N * (K >> 1);
    uint32_t* Wloz = Wlo + (size_t)blockIdx.z * N * (K >> 1);
    int tx = threadIdx.x, ty = threadIdx.y;
    int tid = ty * 32 + tx;
#pragma unroll
    for (int i = 0; i < 32; i += 8)
        t[ty + i][tx] = Wz[(size_t)(k0 + ty + i) * N + n0 + tx];
    __syncthreads();
    int kp = tid & 15, nn = tid >> 4;
    int kpp = (kp & 8) | ((kp & 3) << 1) | ((kp >> 2) & 1);
#pragma unroll
    for (int j = 0; j < 2; j++) {
        int n = nn + 16 * j;
        uint32_t hi, lo;
        split2(t[2 * kp][n], t[2 * kp + 1][n], hi, lo);
        size_t oi = (size_t)(n0 + n) * (K >> 1) + (k0 >> 1) + kpp;
        Whiz[oi] = hi;
        Wloz[oi] = lo;
    }
}

// QKV weight: permuted column n' = kv*512+h*64+d; Q pre-scaled; pair-permuted.
__global__ void wqkvtrans_k(const float* __restrict__ W,
                            uint32_t* __restrict__ Whi, uint32_t* __restrict__ Wlo) {
    int z   = blockIdx.y;
    int idx = blockIdx.x * 256 + threadIdx.x;
    int k2  = idx & 255;
    int np  = idx >> 8;
    int kv  = np >> 9, h = (np >> 6) & 7, d = np & 63;
    int n   = d * 24 + kv * 8 + h;
    const float* Wz = W + (size_t)z * 512 * 1536;
    float x0 = Wz[(size_t)(2 * k2) * 1536 + n];
    float x1 = Wz[(size_t)(2 * k2 + 1) * 1536 + n];
    if (kv == 0) { x0 *= 0.18033688011112042f; x1 *= 0.18033688011112042f; }
    uint32_t hi, lo;
    split2(x0, x1, hi, lo);
    size_t oi = (size_t)z * 1536 * 256 + (size_t)np * 256 + pperm(k2);
    Whi[oi] = hi;
    Wlo[oi] = lo;
}

// ---------------------------------------------------------------------------
// bf16x3 warp-MMA GEMM.  CTA 128x128, 8 warps (64x32), K-chunk 32.
// cp.async 3-stage pipeline (32KB/stage, 96KB total -> 2 CTAs/SM), no
// register prefetch (regs ~110 -> 2 CTAs/SM by regs too).  XOR-swizzled
// unpadded smem (16 u32/row, unit ^= row&3): cp.async 16B stores and
// LDS.64 fragment loads both conflict-free (bank enumeration verified).
// EPI: 0 plain->C, 1 +bias->C, 2 +bias+gelu->hi/lo, 3 QKV scatter
// ---------------------------------------------------------------------------
#define GTILE 2048                     // u32 per tile (128 rows x 16)
#define GSTAGE (4 * GTILE)             // 8192 u32 = 32KB
#define GMM_SMEM (3 * GSTAGE * 4)      // 98304 B

template <int EPI>
__global__ void __launch_bounds__(256) gemm_mma(
    const uint32_t* __restrict__ Ahi, const uint32_t* __restrict__ Alo,
    const uint32_t* __restrict__ Bhi, const uint32_t* __restrict__ Blo,
    const float* __restrict__ bias, float* __restrict__ C,
    uint32_t* __restrict__ O1h, uint32_t* __restrict__ O1l,
    uint32_t* __restrict__ O2h, uint32_t* __restrict__ O2l,
    __nv_bfloat16* __restrict__ O3h, __nv_bfloat16* __restrict__ O3l,
    int M, int N, int K)
{
    extern __shared__ uint32_t sm[];

    const int tid  = threadIdx.x;
    const int wid  = tid >> 5;
    const int lane = tid & 31;
    const int g    = lane >> 2;
    const int cq   = lane & 3;
    const int wm   = (wid & 1) * 64;
    const int wn   = (wid >> 1) * 32;
    const int m0   = blockIdx.y * 128;
    const int n0   = blockIdx.x * 128;
    const int K2   = K >> 1;
    const int NC   = K >> 5;
    const uint32_t sbase = smem_u32(sm);

    const int pu = tid & 3;             // uint4 unit within 16-u32 row
    const int pr = tid >> 2;            // row 0..63 (+64)

    const uint32_t* gbase[4] = {
        Ahi + (size_t)m0 * K2, Alo + (size_t)m0 * K2,
        Bhi + (size_t)n0 * K2, Blo + (size_t)n0 * K2 };

    // per-chunk cp.async issue: 8 x 16B per thread into swizzled stage
    auto issue = [&](int cc) {
        const uint32_t sb = sbase + (uint32_t)((cc % 3) * (GSTAGE * 4));
        const int k4 = cc << 4;
#pragma unroll
        for (int t = 0; t < 4; t++) {
#pragma unroll
            for (int hlf = 0; hlf < 2; hlf++) {
                int r = pr + hlf * 64;
                cp16(sb + (uint32_t)(t * GTILE + r * 16 + ((pu ^ (r & 3)) << 2)) * 4,
                     gbase[t] + (size_t)r * K2 + k4 + pu * 4);
            }
        }
    };

    float acc[4][4][4];
#pragma unroll
    for (int mt = 0; mt < 4; mt++)
#pragma unroll
        for (int nt = 0; nt < 4; nt++)
#pragma unroll
            for (int e = 0; e < 4; e++) acc[mt][nt][e] = 0.0f;

    issue(0); CP_COMMIT();
    issue(1); CP_COMMIT();

    for (int c = 0; c < NC; c++) {
        CP_WAIT1();
        __syncthreads();
        const uint32_t* sp = sm + (c % 3) * GSTAGE;

#pragma unroll
        for (int ks = 0; ks < 2; ks++) {
            const int lu  = ks * 2 + (cq >> 1);   // logical uint4 unit
            const int off = (2 * cq) & 3;         // u32 offset inside unit
            uint32_t bh[4][2], bl[4][2];
#pragma unroll
            for (int nt = 0; nt < 4; nt++) {
                int r = wn + nt * 8 + g;
                int w = r * 16 + ((lu ^ (r & 3)) << 2) + off;
                uint2 vbh = *(const uint2*)&sp[2 * GTILE + w];
                uint2 vbl = *(const uint2*)&sp[3 * GTILE + w];
                bh[nt][0] = vbh.x; bh[nt][1] = vbh.y;
                bl[nt][0] = vbl.x; bl[nt][1] = vbl.y;
            }
#pragma unroll
            for (int mt = 0; mt < 4; mt++) {
                int r0i = wm + mt * 16 + g;
                int r1i = r0i + 8;
                int w0 = r0i * 16 + ((lu ^ (r0i & 3)) << 2) + off;
                int w1 = r1i * 16 + ((lu ^ (r1i & 3)) << 2) + off;
                uint2 a0 = *(const uint2*)&sp[w0];
                uint2 a1 = *(const uint2*)&sp[w1];
                uint2 c0 = *(const uint2*)&sp[GTILE + w0];
                uint2 c1 = *(const uint2*)&sp[GTILE + w1];
                uint32_t ah[4] = {a0.x, a1.x, a0.y, a1.y};
                uint32_t al[4] = {c0.x, c1.x, c0.y, c1.y};
#pragma unroll
                for (int nt = 0; nt < 4; nt++) mma_bf16(acc[mt][nt], ah, bh[nt]);
#pragma unroll
                for (int nt = 0; nt < 4; nt++) mma_bf16(acc[mt][nt], al, bh[nt]);
#pragma unroll
                for (int nt = 0; nt < 4; nt++) mma_bf16(acc[mt][nt], ah, bl[nt]);
            }
        }

        if (c + 2 < NC) issue(c + 2);
        CP_COMMIT();
    }

    // ---- epilogue ----
#pragma unroll
    for (int mt = 0; mt < 4; mt++) {
#pragma unroll
        for (int nt = 0; nt < 4; nt++) {
            int col = n0 + wn + nt * 8 + 2 * cq;
            int r0  = m0 + wm + mt * 16 + g;
            float2 v0 = make_float2(acc[mt][nt][0], acc[mt][nt][1]);
            float2 v1 = make_float2(acc[mt][nt][2], acc[mt][nt][3]);
            if (EPI == 3) {
                int kv = col >> 9, h = (col >> 6) & 7, d = col & 63;
                int b0i = r0 >> 11, t0i = r0 & (SEQ - 1);
                int t1i = (r0 + 8) & (SEQ - 1);
                if (kv == 2) {
                    size_t base0 = (((size_t)b0i * NHEADS + h) * DHEAD + d) * SEQ;
                    int et0 = eperm(t0i), et1 = eperm(t1i);
                    __nv_bfloat16 h00 = __float2bfloat16_rn(v0.x);
                    __nv_bfloat16 h01 = __float2bfloat16_rn(v0.y);
                    __nv_bfloat16 h10 = __float2bfloat16_rn(v1.x);
                    __nv_bfloat16 h11 = __float2bfloat16_rn(v1.y);
                    O3h[base0 + et0]       = h00;
                    O3h[base0 + SEQ + et0] = h01;
                    O3h[base0 + et1]       = h10;
                    O3h[base0 + SEQ + et1] = h11;
                    O3l[base0 + et0]       = __float2bfloat16_rn(v0.x - __bfloat162float(h00));
                    O3l[base0 + SEQ + et0] = __float2bfloat16_rn(v0.y - __bfloat162float(h01));
                    O3l[base0 + et1]       = __float2bfloat16_rn(v1.x - __bfloat162float(h10));
                    O3l[base0 + SEQ + et1] = __float2bfloat16_rn(v1.y - __bfloat162float(h11));
                } else {
                    uint32_t* dh = (kv == 0) ? O1h : O2h;
                    uint32_t* dl = (kv == 0) ? O1l : O2l;
                    uint32_t hi0, lo0, hi1, lo1;
                    split2(v0.x, v0.y, hi0, lo0);
                    split2(v1.x, v1.y, hi1, lo1);
                    int dp = pperm(d >> 1);
                    size_t qi0 = (((size_t)b0i * NHEADS + h) * SEQ + t0i) * 32 + dp;
                    size_t qi1 = (((size_t)b0i * NHEADS + h) * SEQ + t1i) * 32 + dp;
                    dh[qi0] = hi0; dl[qi0] = lo0;
                    dh[qi1] = hi1; dl[qi1] = lo1;
                }
            } else if (EPI == 2) {
                float2 bb = *(const float2*)(bias + col);
                v0.x = gelu_exact(v0.x + bb.x); v0.y = gelu_exact(v0.y + bb.y);
                v1.x = gelu_exact(v1.x + bb.x); v1.y = gelu_exact(v1.y + bb.y);
                uint32_t hi0, lo0, hi1, lo1;
                split2(v0.x, v0.y, hi0, lo0);
                split2(v1.x, v1.y, hi1, lo1);
                int cp = pperm(col >> 1);
                size_t oi0 = (size_t)r0 * (N >> 1) + cp;
                size_t oi1 = (size_t)(r0 + 8) * (N >> 1) + cp;
                O1h[oi0] = hi0; O1l[oi0] = lo0;
                O1h[oi1] = hi1; O1l[oi1] = lo1;
            } else {
                if (EPI == 1) {
                    float2 bb = *(const float2*)(bias + col);
                    v0.x += bb.x; v0.y += bb.y;
                    v1.x += bb.x; v1.y += bb.y;
                }
                *(float2*)(C + (size_t)r0 * N + col)       = v0;
                *(float2*)(C + (size_t)(r0 + 8) * N + col) = v1;
            }
        }
    }
}

// ---------------------------------------------------------------------------
// Flash attention, bf16x3 mma.sync, pre-split permuted inputs.
// Smem stride 40 u32 (conflict-free LDS.64).
// ---------------------------------------------------------------------------
#define FSC 40
#define FQH 0
#define FQL 5120
#define FKH 10240
#define FKL 12800
#define FVH 15360
#define FVL 17920
#define FLASH2_SMEM (20480 * 4)

__global__ void __launch_bounds__(256, 2) flash_mma(
    const uint32_t* __restrict__ Qhi, const uint32_t* __restrict__ Qlo,
    const uint32_t* __restrict__ Khi, const uint32_t* __restrict__ Klo,
    const __nv_bfloat16* __restrict__ Vhi, const __nv_bfloat16* __restrict__ Vlo,
    uint32_t* __restrict__ Ohi, uint32_t* __restrict__ Olo)
{
    extern __shared__ uint32_t sm[];
    const int tid  = threadIdx.x;
    const int wid  = tid >> 5;
    const int lane = tid & 31;
    const int g    = lane >> 2;
    const int cq   = lane & 3;
    const int t0   = blockIdx.x * 128;
    const int h    = blockIdx.y;
    const int b    = blockIdx.z;
    const size_t bh = ((size_t)b * NHEADS + h) * SEQ;

    {
        int row = tid >> 1;
        const uint2* qh = (const uint2*)(Qhi + (bh + t0 + row) * 32);
        const uint2* ql = (const uint2*)(Qlo + (bh + t0 + row) * 32);
#pragma unroll
        for (int i = 0; i < 8; i++) {
            int f4 = (tid & 1) + 2 * i;
            uint2 a = qh[f4], bq = ql[f4];
            int di = row * FSC + f4 * 2;
            sm[FQH + di] = a.x;  sm[FQH + di + 1] = a.y;
            sm[FQL + di] = bq.x; sm[FQL + di + 1] = bq.y;
        }
    }

    float o[8][4];
#pragma unroll
    for (int dt = 0; dt < 8; dt++)
#pragma unroll
        for (int e = 0; e < 4; e++) o[dt][e] = 0.0f;
    float m0 = -1e30f, m1 = -1e30f, l0 = 0.0f, l1 = 0.0f;

    const int prow = tid >> 2;
    const __nv_bfloat16* vhrow = Vhi + ((((size_t)b * NHEADS + h) * DHEAD) + prow) * SEQ;
    const __nv_bfloat16* vlrow = Vlo + ((((size_t)b * NHEADS + h) * DHEAD) + prow) * SEQ;
    const int qr = wid * 16 + g;

    for (int jb = 0; jb < SEQ; jb += 64) {
        __syncthreads();
        const uint2* kh2 = (const uint2*)(Khi + (bh + jb + prow) * 32);
        const uint2* kl2 = (const uint2*)(Klo + (bh + jb + prow) * 32);
        const uint2* vh2 = (const uint2*)(vhrow + jb);
        const uint2* vl2 = (const uint2*)(vlrow + jb);
#pragma unroll
        for (int i = 0; i < 4; i++) {
            int f4 = (tid & 3) + i * 4;
            int di = prow * FSC + f4 * 2;
            uint2 a = kh2[f4], c2 = kl2[f4];
            sm[FKH + di] = a.x;  sm[FKH + di + 1] = a.y;
            sm[FKL + di] = c2.x; sm[FKL + di + 1] = c2.y;
            uint2 w = vh2[f4], z2 = vl2[f4];
            sm[FVH + di] = w.x;  sm[FVH + di + 1] = w.y;
            sm[FVL + di] = z2.x; sm[FVL + di + 1] = z2.y;
        }
        __syncthreads();

        float s[8][4];
#pragma unroll
        for (int nt = 0; nt < 8; nt++)
#pragma unroll
            for (int e = 0; e < 4; e++) s[nt][e] = 0.0f;

#pragma unroll
        for (int ks = 0; ks < 4; ks++) {
            int qi = qr * FSC + ks * 8 + 2 * cq;
            uint2 q0 = *(const uint2*)&sm[FQH + qi];
            uint2 q1 = *(const uint2*)&sm[FQH + qi + 8 * FSC];
            uint2 r0 = *(const uint2*)&sm[FQL + qi];
            uint2 r1 = *(const uint2*)&sm[FQL + qi + 8 * FSC];
            uint32_t qh[4] = {q0.x, q1.x, q0.y, q1.y};
            uint32_t ql[4] = {r0.x, r1.x, r0.y, r1.y};
            uint32_t kh[8][2], kl[8][2];
#pragma unroll
            for (int nt = 0; nt < 8; nt++) {
                int ki = (nt * 8 + g) * FSC + ks * 8 + 2 * cq;
                uint2 vk = *(const uint2*)&sm[FKH + ki];
                uint2 wk = *(const uint2*)&sm[FKL + ki];
                kh[nt][0] = vk.x; kh[nt][1] = vk.y;
                kl[nt][0] = wk.x; kl[nt][1] = wk.y;
            }
#pragma unroll
            for (int nt = 0; nt < 8; nt++) mma_bf16(s[nt], qh, kh[nt]);
#pragma unroll
            for (int nt = 0; nt < 8; nt++) mma_bf16(s[nt], ql, kh[nt]);
#pragma unroll
            for (int nt = 0; nt < 8; nt++) mma_bf16(s[nt], qh, kl[nt]);
        }

        float rm0 = -1e30f, rm1 = -1e30f;
#pragma unroll
        for (int nt = 0; nt < 8; nt++) {
            rm0 = fmaxf(rm0, fmaxf(s[nt][0], s[nt][1]));
            rm1 = fmaxf(rm1, fmaxf(s[nt][2], s[nt][3]));
        }
        rm0 = fmaxf(rm0, __shfl_xor_sync(0xffffffffu, rm0, 1));
        rm0 = fmaxf(rm0, __shfl_xor_sync(0xffffffffu, rm0, 2));
        rm1 = fmaxf(rm1, __shfl_xor_sync(0xffffffffu, rm1, 1));
        rm1 = fmaxf(rm1, __shfl_xor_sync(0xffffffffu, rm1, 2));
        float mn0 = fmaxf(m0, rm0), mn1 = fmaxf(m1, rm1);
        float c0 = exp2f(m0 - mn0), c1 = exp2f(m1 - mn1);
        m0 = mn0; m1 = mn1;
        float rs0 = 0.0f, rs1 = 0.0f;
#pragma unroll
        for (int nt = 0; nt < 8; nt++) {
            s[nt][0] = exp2f(s[nt][0] - mn0);
            s[nt][1] = exp2f(s[nt][1] - mn0);
            s[nt][2] = exp2f(s[nt][2] - mn1);
            s[nt][3] = exp2f(s[nt][3] - mn1);
            rs0 += s[nt][0] + s[nt][1];
            rs1 += s[nt][2] + s[nt][3];
        }
        rs0 += __shfl_xor_sync(0xffffffffu, rs0, 1);
        rs0 += __shfl_xor_sync(0xffffffffu, rs0, 2);
        rs1 += __shfl_xor_sync(0xffffffffu, rs1, 1);
        rs1 += __shfl_xor_sync(0xffffffffu, rs1, 2);
        l0 = l0 * c0 + rs0;
        l1 = l1 * c1 + rs1;
#pragma unroll
        for (int dt = 0; dt < 8; dt++) {
            o[dt][0] *= c0; o[dt][1] *= c0;
            o[dt][2] *= c1; o[dt][3] *= c1;
        }

        uint32_t ph[4][4], pl[4][4];
#pragma unroll
        for (int kj = 0; kj < 4; kj++) {
            split2(s[2*kj][0],   s[2*kj][1],   ph[kj][0], pl[kj][0]);
            split2(s[2*kj][2],   s[2*kj][3],   ph[kj][1], pl[kj][1]);
            split2(s[2*kj+1][0], s[2*kj+1][1], ph[kj][2], pl[kj][2]);
            split2(s[2*kj+1][2], s[2*kj+1][3], ph[kj][3], pl[kj][3]);
        }

#pragma unroll
        for (int kj = 0; kj < 4; kj++) {
            uint32_t vh[8][2], vl[8][2];
#pragma unroll
            for (int dt = 0; dt < 8; dt++) {
                int vi = (dt * 8 + g) * FSC + kj * 8 + 2 * cq;
                uint2 a = *(const uint2*)&sm[FVH + vi];
                uint2 c2 = *(const uint2*)&sm[FVL + vi];
                vh[dt][0] = a.x;  vh[dt][1] = a.y;
                vl[dt][0] = c2.x; vl[dt][1] = c2.y;
            }
#pragma unroll
            for (int dt = 0; dt < 8; dt++) mma_bf16(o[dt], ph[kj], vh[dt]);
#pragma unroll
            for (int dt = 0; dt < 8; dt++) mma_bf16(o[dt], pl[kj], vh[dt]);
#pragma unroll
            for (int dt = 0; dt < 8; dt++) mma_bf16(o[dt], ph[kj], vl[dt]);
        }
    }

    float inv0 = 1.0f / l0, inv1 = 1.0f / l1;
    int row0 = t0 + wid * 16 + g;
#pragma unroll
    for (int dt = 0; dt < 8; dt++) {
        int col = h * DHEAD + dt * 8 + 2 * cq;
        int cp = pperm(col >> 1);
        uint32_t hi, lo;
        split2(o[dt][0] * inv0, o[dt][1] * inv0, hi, lo);
        size_t oi0 = ((size_t)b * SEQ + row0) * 256 + cp;
        Ohi[oi0] = hi; Olo[oi0] = lo;
        split2(o[dt][2] * inv1, o[dt][3] * inv1, hi, lo);
        size_t oi1 = ((size_t)b * SEQ + row0 + 8) * 256 + cp;
        Ohi[oi1] = hi; Olo[oi1] = lo;
    }
}

// ---------------------------------------------------------------------------
// out = LayerNorm(a + resid) -> fp32 + hi/lo (permuted)
// ---------------------------------------------------------------------------
__global__ void __launch_bounds__(128) add_ln_k(
    const float* __restrict__ A, const float* __restrict__ R,
    const float* __restrict__ g, const float* __restrict__ bb,
    float* __restrict__ out, uint32_t* __restrict__ Ohi, uint32_t* __restrict__ Olo)
{
    __shared__ float red[4];
    int row = blockIdx.x;
    int tid = threadIdx.x;
    int warp = tid >> 5, lane = tid & 31;

    float4 a4 = *(const float4*)(A + (size_t)row * DMODEL + tid * 4);
    float4 r4 = *(const float4*)(R + (size_t)row * DMODEL + tid * 4);
    float x0 = a4.x + r4.x, x1 = a4.y + r4.y, x2 = a4.z + r4.z, x3 = a4.w + r4.w;

    float s = x0 + x1 + x2 + x3;
    s += __shfl_xor_sync(0xffffffffu, s, 16);
    s += __shfl_xor_sync(0xffffffffu, s, 8);
    s += __shfl_xor_sync(0xffffffffu, s, 4);
    s += __shfl_xor_sync(0xffffffffu, s, 2);
    s += __shfl_xor_sync(0xffffffffu, s, 1);
    if (lane == 0) red[warp] = s;
    __syncthreads();
    float mu = (red[0] + red[1] + red[2] + red[3]) * (1.0f / DMODEL);
    __syncthreads();

    float d0 = x0 - mu, d1 = x1 - mu, d2 = x2 - mu, d3 = x3 - mu;
    float s2 = d0*d0 + d1*d1 + d2*d2 + d3*d3;
    s2 += __shfl_xor_sync(0xffffffffu, s2, 16);
    s2 += __shfl_xor_sync(0xffffffffu, s2, 8);
    s2 += __shfl_xor_sync(0xffffffffu, s2, 4);
    s2 += __shfl_xor_sync(0xffffffffu, s2, 2);
    s2 += __shfl_xor_sync(0xffffffffu, s2, 1);
    if (lane == 0) red[warp] = s2;
    __syncthreads();
    float var = (red[0] + red[1] + red[2] + red[3]) * (1.0f / DMODEL);
    float rstd = rsqrtf(var + 1e-5f);

    float4 gv = *(const float4*)(g  + tid * 4);
    float4 bv = *(const float4*)(bb + tid * 4);
    float4 ov = make_float4(d0 * rstd * gv.x + bv.x,
                            d1 * rstd * gv.y + bv.y,
                            d2 * rstd * gv.z + bv.z,
                            d3 * rstd * gv.w + bv.w);
    *(float4*)(out + (size_t)row * DMODEL + tid * 4) = ov;
    uint32_t h0, l0, h1, l1;
    split2(ov.x, ov.y, h0, l0);
    split2(ov.z, ov.w, h1, l1);
    int p0 = tid * 2;
    size_t rb = (size_t)row * 256;
    Ohi[rb + pperm(p0)]     = h0; Olo[rb + pperm(p0)]     = l0;
    Ohi[rb + pperm(p0 + 1)] = h1; Olo[rb + pperm(p0 + 1)] = l1;
}

// ---------------------------------------------------------------------------
// Head
// ---------------------------------------------------------------------------
__global__ void head_k(const float* __restrict__ H, const float* __restrict__ W,
                       const float* __restrict__ bh, float* __restrict__ out)
{
    int gw   = (blockIdx.x * blockDim.x + threadIdx.x) >> 5;
    int lane = threadIdx.x & 31;
    const float* r = H + (size_t)gw * DMODEL;
    float s = 0.0f;
#pragma unroll
    for (int k = 0; k < DMODEL / 32; k++)
        s = fmaf(r[lane + k * 32], W[lane + k * 32], s);
    s += __shfl_xor_sync(0xffffffffu, s, 16);
    s += __shfl_xor_sync(0xffffffffu, s, 8);
    s += __shfl_xor_sync(0xffffffffu, s, 4);
    s += __shfl_xor_sync(0xffffffffu, s, 2);
    s += __shfl_xor_sync(0xffffffffu, s, 1);
    if (lane == 0) out[gw] = s + bh[0];
}

// ---------------------------------------------------------------------------
// Launcher
// ---------------------------------------------------------------------------
extern "C" void kernel_launch(void* const* d_in, const int* in_sizes, int n_in,
                              void* d_out, int out_size)
{
    const int*   x     = (const int*)  d_in[0];
    const float* embed = (const float*)d_in[1];
    const float* pe    = (const float*)d_in[2];
    const float* Wqkv  = (const float*)d_in[3];
    const float* W0    = (const float*)d_in[4];
    const float* g1    = (const float*)d_in[5];
    const float* b1    = (const float*)d_in[6];
    const float* g2    = (const float*)d_in[7];
    const float* b2    = (const float*)d_in[8];
    const float* Wl1   = (const float*)d_in[9];
    const float* bl1   = (const float*)d_in[10];
    const float* Wl2   = (const float*)d_in[11];
    const float* bl2   = (const float*)d_in[12];
    const float* Wh    = (const float*)d_in[13];
    const float* bh    = (const float*)d_in[14];
    float* out = (float*)d_out;

    float *hb, *yb, *ab;
    uint32_t *hhi, *hlo, *yhi, *ylo, *aohi, *aolo, *midhi, *midlo;
    uint32_t *qhi, *qlo, *khi, *klo;
    __nv_bfloat16 *vhi, *vlo;
    uint32_t *wqh, *wql, *w0h, *w0l, *l1h, *l1l, *l2h, *l2l;
    cudaGetSymbolAddress((void**)&hb,    g_h);
    cudaGetSymbolAddress((void**)&yb,    g_y);
    cudaGetSymbolAddress((void**)&ab,    g_a);
    cudaGetSymbolAddress((void**)&hhi,   g_hhi);  cudaGetSymbolAddress((void**)&hlo,   g_hlo);
    cudaGetSymbolAddress((void**)&yhi,   g_yhi);  cudaGetSymbolAddress((void**)&ylo,   g_ylo);
    cudaGetSymbolAddress((void**)&aohi,  g_aohi); cudaGetSymbolAddress((void**)&aolo,  g_aolo);
    cudaGetSymbolAddress((void**)&midhi, g_midhi);cudaGetSymbolAddress((void**)&midlo, g_midlo);
    cudaGetSymbolAddress((void**)&qhi,   g_qhi);  cudaGetSymbolAddress((void**)&qlo,   g_qlo);
    cudaGetSymbolAddress((void**)&khi,   g_khi);  cudaGetSymbolAddress((void**)&klo,   g_klo);
    cudaGetSymbolAddress((void**)&vhi,   g_vhi);  cudaGetSymbolAddress((void**)&vlo,   g_vlo);
    cudaGetSymbolAddress((void**)&wqh,   g_wqkv_hi); cudaGetSymbolAddress((void**)&wql, g_wqkv_lo);
    cudaGetSymbolAddress((void**)&w0h,   g_w0_hi);   cudaGetSymbolAddress((void**)&w0l, g_w0_lo);
    cudaGetSymbolAddress((void**)&l1h,   g_l1_hi);   cudaGetSymbolAddress((void**)&l1l, g_l1_lo);
    cudaGetSymbolAddress((void**)&l2h,   g_l2_hi);   cudaGetSymbolAddress((void**)&l2l, g_l2_lo);

    cudaFuncSetAttribute(flash_mma, cudaFuncAttributeMaxDynamicSharedMemorySize, FLASH2_SMEM);
    cudaFuncSetAttribute(gemm_mma<0>, cudaFuncAttributeMaxDynamicSharedMemorySize, GMM_SMEM);
    cudaFuncSetAttribute(gemm_mma<1>, cudaFuncAttributeMaxDynamicSharedMemorySize, GMM_SMEM);
    cudaFuncSetAttribute(gemm_mma<2>, cudaFuncAttributeMaxDynamicSharedMemorySize, GMM_SMEM);
    cudaFuncSetAttribute(gemm_mma<3>, cudaFuncAttributeMaxDynamicSharedMemorySize, GMM_SMEM);

    wqkvtrans_k<<<dim3((1536 * 256) / 256, NBLOCKS), 256>>>(Wqkv, wqh, wql);
    wtrans_k<<<dim3(16, 16, NBLOCKS), dim3(32, 8)>>>(W0,  w0h, w0l, DMODEL, DMODEL);
    wtrans_k<<<dim3(64, 16, NBLOCKS), dim3(32, 8)>>>(Wl1, l1h, l1l, DMODEL, DFF);
    wtrans_k<<<dim3(16, 64, NBLOCKS), dim3(32, 8)>>>(Wl2, l2h, l2l, DFF, DMODEL);

    embed_k<<<(NROWS * (DMODEL / 4)) / 256, 256>>>(x, embed, pe, hb, hhi, hlo);

    for (int i = 0; i < NBLOCKS; i++) {
        gemm_mma<3><<<dim3(12, 64), 256, GMM_SMEM>>>(
            hhi, hlo, wqh + (size_t)i * 1536 * 256, wql + (size_t)i * 1536 * 256,
            nullptr, nullptr, qhi, qlo, khi, klo, vhi, vlo,
            NROWS, 3 * DMODEL, DMODEL);

        flash_mma<<<dim3(SEQ / 128, NHEADS, BATCH), 256, FLASH2_SMEM>>>(
            qhi, qlo, khi, klo, vhi, vlo, aohi, aolo);

        gemm_mma<0><<<dim3(4, 64), 256, GMM_SMEM>>>(
            aohi, aolo, w0h + (size_t)i * 512 * 256, w0l + (size_t)i * 512 * 256,
            nullptr, ab, nullptr, nullptr, nullptr, nullptr, nullptr, nullptr,
            NROWS, DMODEL, DMODEL);

        add_ln_k<<<NROWS, 128>>>(ab, hb, g1 + i * DMODEL, b1 + i * DMODEL, yb, yhi, ylo);

        gemm_mma<2><<<dim3(16, 64), 256, GMM_SMEM>>>(
            yhi, ylo, l1h + (size_t)i * 2048 * 256, l1l + (size_t)i * 2048 * 256,
            bl1 + i * DFF, nullptr, midhi, midlo, nullptr, nullptr, nullptr, nullptr,
            NROWS, DFF, DMODEL);

        gemm_mma<1><<<dim3(4, 64), 256, GMM_SMEM>>>(
            midhi, midlo, l2h + (size_t)i * 512 * 1024, l2l + (size_t)i * 512 * 1024,
            bl2 + i * DMODEL, ab, nullptr, nullptr, nullptr, nullptr, nullptr, nullptr,
            NROWS, DMODEL, DFF);

        add_ln_k<<<NROWS, 128>>>(ab, yb, g2 + i * DMODEL, b2 + i * DMODEL, hb, hhi, hlo);
    }

    head_k<<<NROWS / 8, 256>>>(hb, Wh, bh, out);
}

// round 14
// speedup vs baseline: 1.1254x; 1.1079x over previous
#include <cuda_runtime.h>
#include <cuda_bf16.h>
#include <cstdint>
#include <math.h>

// Problem constants
#define BATCH  4
#define SEQ    2048
#define DMODEL 512
#define NHEADS 8
#define DHEAD  64
#define DFF    2048
#define NBLOCKS 6
#define NROWS  (BATCH * SEQ)   // 8192

// ---------------------------------------------------------------------------
// Scratch (device globals)
// ---------------------------------------------------------------------------
__device__ float g_h  [NROWS * DMODEL];
__device__ float g_y  [NROWS * DMODEL];
__device__ float g_a  [NROWS * DMODEL];
__device__ float g_ao [NROWS * DMODEL];
__device__ float g_q  [BATCH * NHEADS * SEQ * DHEAD];
__device__ float g_k  [BATCH * NHEADS * SEQ * DHEAD];
__device__ float g_v  [BATCH * NHEADS * DHEAD * SEQ];   // transposed [B,H,D,T]
__device__ float g_mid[NROWS * DFF];
// Transposed weights, [N][K] K-major
__device__ float g_wt_qkv[NBLOCKS * 3 * DMODEL * DMODEL];
__device__ float g_wt_w0 [NBLOCKS * DMODEL * DMODEL];
__device__ float g_wt_l1 [NBLOCKS * DFF * DMODEL];
__device__ float g_wt_l2 [NBLOCKS * DMODEL * DFF];

__device__ __forceinline__ float gelu_exact(float x) {
    return 0.5f * x * (1.0f + erff(x * 0.70710678118654752f));
}

// ---------------------------------------------------------------------------
// bf16 split: x = hi + lo
// ---------------------------------------------------------------------------
__device__ __forceinline__ void split2(float x, float y, uint32_t& hi, uint32_t& lo) {
    __nv_bfloat16 hx = __float2bfloat16_rn(x);
    __nv_bfloat16 hy = __float2bfloat16_rn(y);
    float rx = x - __bfloat162float(hx);
    float ry = y - __bfloat162float(hy);
    __nv_bfloat162 H; H.x = hx; H.y = hy;
    __nv_bfloat162 L = __floats2bfloat162_rn(rx, ry);
    hi = *reinterpret_cast<uint32_t*>(&H);
    lo = *reinterpret_cast<uint32_t*>(&L);
}

__device__ __forceinline__ uint32_t pack_bf16x2(float x, float y) {
    __nv_bfloat162 H = __floats2bfloat162_rn(x, y);
    return *reinterpret_cast<uint32_t*>(&H);
}

__device__ __forceinline__ void mma_bf16(float* c, const uint32_t* a, const uint32_t* b) {
    asm volatile(
        "mma.sync.aligned.m16n8k16.row.col.f32.bf16.bf16.f32 "
        "{%0,%1,%2,%3}, {%4,%5,%6,%7}, {%8,%9}, {%0,%1,%2,%3};"
        : "+f"(c[0]), "+f"(c[1]), "+f"(c[2]), "+f"(c[3])
        : "r"(a[0]), "r"(a[1]), "r"(a[2]), "r"(a[3]), "r"(b[0]), "r"(b[1]));
}

// ---------------------------------------------------------------------------
// Embedding + sinusoidal PE
// ---------------------------------------------------------------------------
__global__ void embed_k(const int* __restrict__ x, const float* __restrict__ E,
                        const float* __restrict__ pe, float* __restrict__ H) {
    int idx = blockIdx.x * blockDim.x + threadIdx.x;
    int row = idx >> 7;
    int c   = (idx & 127) << 2;
    int t   = row & (SEQ - 1);
    int tok = x[row];
    float4 e = *(const float4*)(E  + (size_t)tok * DMODEL + c);
    float4 p = *(const float4*)(pe + (size_t)t   * DMODEL + c);
    *(float4*)(H + (size_t)row * DMODEL + c) =
        make_float4(e.x + p.x, e.y + p.y, e.z + p.z, e.w + p.w);
}

// ---------------------------------------------------------------------------
// Weight transposes
// ---------------------------------------------------------------------------
__global__ void wtrans_k(const float* __restrict__ W, float* __restrict__ Wt,
                         int K, int N) {
    __shared__ float t[32][33];
    int n0 = blockIdx.x * 32, k0 = blockIdx.y * 32;
    const float* Wz = W  + (size_t)blockIdx.z * K * N;
    float*      Wtz = Wt + (size_t)blockIdx.z * K * N;
    int tx = threadIdx.x, ty = threadIdx.y;
#pragma unroll
    for (int i = 0; i < 32; i += 8)
        t[ty + i][tx] = Wz[(size_t)(k0 + ty + i) * N + n0 + tx];
    __syncthreads();
#pragma unroll
    for (int i = 0; i < 32; i += 8)
        Wtz[(size_t)(n0 + ty + i) * K + k0 + tx] = t[tx][ty + i];
}

__global__ void wqkvtrans_k(const float* __restrict__ W, float* __restrict__ Wt) {
    int z   = blockIdx.y;
    int idx = blockIdx.x * 256 + threadIdx.x;
    int k   = idx & 511;
    int np  = idx >> 9;
    int kv  = np >> 9, h = (np >> 6) & 7, d = np & 63;
    int n   = d * 24 + kv * 8 + h;
    float w = W[((size_t)z * 512 + k) * 1536 + n];
    if (kv == 0) w *= 0.18033688011112042f;   // fold 0.125*log2(e) into Q
    Wt[(size_t)z * 1536 * 512 + idx] = w;
}

// ---------------------------------------------------------------------------
// bf16x3 warp-MMA GEMM (round-5 proven, unchanged)
// EPI: 0 plain, 1 +bias, 2 +bias+gelu, 3 QKV scatter (V transposed)
// ---------------------------------------------------------------------------
#define GST 10240
#define GMM_SMEM (2 * GST * 4)

template <int EPI>
__global__ void __launch_bounds__(256) gemm_mma(
    const float* __restrict__ A, const float* __restrict__ Bt,
    const float* __restrict__ bias, float* __restrict__ C,
    float* __restrict__ Qo, float* __restrict__ Ko, float* __restrict__ Vo,
    int M, int N, int K)
{
    extern __shared__ uint32_t sm[];

    const int tid  = threadIdx.x;
    const int wid  = tid >> 5;
    const int lane = tid & 31;
    const int g    = lane >> 2;
    const int cq   = lane & 3;
    const int wm   = (wid & 1) * 64;
    const int wn   = (wid >> 1) * 32;
    const int m0   = blockIdx.y * 128;
    const int n0   = blockIdx.x * 128;

    const int col4 = tid & 7;
    const int rb   = tid >> 3;

    const float* Ap = A  + (size_t)(m0 + rb) * K + col4 * 4;
    const float* Bp = Bt + (size_t)(n0 + rb) * K + col4 * 4;

    float acc[4][4][4];
#pragma unroll
    for (int mt = 0; mt < 4; mt++)
#pragma unroll
        for (int nt = 0; nt < 4; nt++)
#pragma unroll
            for (int e = 0; e < 4; e++) acc[mt][nt][e] = 0.0f;

    const int NC = K >> 5;

    float4 pa[4], pb[4];
#pragma unroll
    for (int i = 0; i < 4; i++) {
        pa[i] = *(const float4*)(Ap + (size_t)(32 * i) * K);
        pb[i] = *(const float4*)(Bp + (size_t)(32 * i) * K);
    }

    for (int c = 0; c < NC; c++) {
        const int p = c & 1;
        uint32_t* sp = sm + p * GST;

#pragma unroll
        for (int i = 0; i < 4; i++) {
            int di = (rb + 32 * i) * 20 + col4 * 2;
            uint32_t h0, l0, h1, l1;
            split2(pa[i].x, pa[i].y, h0, l0);
            split2(pa[i].z, pa[i].w, h1, l1);
            *reinterpret_cast<uint2*>(sp + di)        = make_uint2(h0, h1);
            *reinterpret_cast<uint2*>(sp + 2560 + di) = make_uint2(l0, l1);
            split2(pb[i].x, pb[i].y, h0, l0);
            split2(pb[i].z, pb[i].w, h1, l1);
            *reinterpret_cast<uint2*>(sp + 5120 + di) = make_uint2(h0, h1);
            *reinterpret_cast<uint2*>(sp + 7680 + di) = make_uint2(l0, l1);
        }
        __syncthreads();

        if (c + 1 < NC) {
            const float* Apn = Ap + (c + 1) * 32;
            const float* Bpn = Bp + (c + 1) * 32;
#pragma unroll
            for (int i = 0; i < 4; i++) {
                pa[i] = *(const float4*)(Apn + (size_t)(32 * i) * K);
                pb[i] = *(const float4*)(Bpn + (size_t)(32 * i) * K);
            }
        }

#pragma unroll
        for (int ks = 0; ks < 2; ks++) {
            const int kb = ks * 8;
            uint32_t bh[4][2], bl[4][2];
#pragma unroll
            for (int nt = 0; nt < 4; nt++) {
                int bi = 5120 + (wn + nt * 8 + g) * 20 + kb + cq;
                bh[nt][0] = sp[bi];
                bh[nt][1] = sp[bi + 4];
                bl[nt][0] = sp[bi + 2560];
                bl[nt][1] = sp[bi + 2560 + 4];
            }
#pragma unroll
            for (int mt = 0; mt < 4; mt++) {
                int ai = (wm + mt * 16 + g) * 20 + kb + cq;
                uint32_t ah[4], al[4];
                ah[0] = sp[ai];             ah[1] = sp[ai + 160];
                ah[2] = sp[ai + 4];         ah[3] = sp[ai + 160 + 4];
                al[0] = sp[ai + 2560];      al[1] = sp[ai + 2560 + 160];
                al[2] = sp[ai + 2560 + 4];  al[3] = sp[ai + 2560 + 160 + 4];
#pragma unroll
                for (int nt = 0; nt < 4; nt++) mma_bf16(acc[mt][nt], ah, bh[nt]);
#pragma unroll
                for (int nt = 0; nt < 4; nt++) mma_bf16(acc[mt][nt], al, bh[nt]);
#pragma unroll
                for (int nt = 0; nt < 4; nt++) mma_bf16(acc[mt][nt], ah, bl[nt]);
            }
        }
    }

#pragma unroll
    for (int mt = 0; mt < 4; mt++) {
#pragma unroll
        for (int nt = 0; nt < 4; nt++) {
            int col = n0 + wn + nt * 8 + 2 * cq;
            int r0  = m0 + wm + mt * 16 + g;
            float2 v0 = make_float2(acc[mt][nt][0], acc[mt][nt][1]);
            float2 v1 = make_float2(acc[mt][nt][2], acc[mt][nt][3]);
            if (EPI == 3) {
                int kv = col >> 9, h = (col >> 6) & 7, d = col & 63;
                int b0i = r0 >> 11, t0i = r0 & (SEQ - 1);
                int r1 = r0 + 8;
                int b1i = r1 >> 11, t1i = r1 & (SEQ - 1);
                if (kv == 2) {
                    size_t base0 = (((size_t)b0i * NHEADS + h) * DHEAD + d) * SEQ;
                    size_t base1 = (((size_t)b1i * NHEADS + h) * DHEAD + d) * SEQ;
                    Vo[base0 + t0i]       = v0.x;
                    Vo[base0 + SEQ + t0i] = v0.y;
                    Vo[base1 + t1i]       = v1.x;
                    Vo[base1 + SEQ + t1i] = v1.y;
                } else {
                    float* dst = (kv == 0) ? Qo : Ko;
                    *(float2*)(dst + (((size_t)b0i * NHEADS + h) * SEQ + t0i) * DHEAD + d) = v0;
                    *(float2*)(dst + (((size_t)b1i * NHEADS + h) * SEQ + t1i) * DHEAD + d) = v1;
                }
            } else {
                if (EPI >= 1) {
                    float2 bb = *(const float2*)(bias + col);
                    v0.x += bb.x; v0.y += bb.y;
                    v1.x += bb.x; v1.y += bb.y;
                }
                if (EPI == 2) {
                    v0.x = gelu_exact(v0.x); v0.y = gelu_exact(v0.y);
                    v1.x = gelu_exact(v1.x); v1.y = gelu_exact(v1.y);
                }
                *(float2*)(C + (size_t)r0 * N + col)       = v0;
                *(float2*)(C + (size_t)(r0 + 8) * N + col) = v1;
            }
        }
    }
}

// ---------------------------------------------------------------------------
// Flash attention, reduced-compensation bf16 mma.sync.
// S = Qhi·(Khi + Klo)  (Q plain bf16; K compensated)
// O = Phi·(Vhi + Vlo)  (P plain bf16; V compensated)
// CTA = 128 queries x 64-key blocks, 8 warps.  Smem stride 36 u32.
// Q prescaled by 0.125*log2(e) (folded into Wq).
// ---------------------------------------------------------------------------
#define FSC 36
#define FQH 0
#define FKH 4608
#define FKL 6912
#define FVH 9216
#define FVL 11520
#define FLASH2_SMEM (13824 * 4)

__global__ void __launch_bounds__(256, 2) flash_mma(
    const float* __restrict__ Q, const float* __restrict__ Kg,
    const float* __restrict__ Vt, float* __restrict__ O)
{
    extern __shared__ uint32_t sm[];
    const int tid  = threadIdx.x;
    const int wid  = tid >> 5;
    const int lane = tid & 31;
    const int g    = lane >> 2;
    const int cq   = lane & 3;
    const int t0   = blockIdx.x * 128;
    const int h    = blockIdx.y;
    const int b    = blockIdx.z;
    const size_t bh = ((size_t)b * NHEADS + h) * SEQ;

    // ---- load Q (prescaled in weights; plain bf16) ----
    {
        int row = tid >> 1;
        const float* qp = Q + (bh + t0 + row) * DHEAD;
#pragma unroll
        for (int i = 0; i < 8; i++) {
            int f4 = (tid & 1) + 2 * i;
            float4 v = *(const float4*)(qp + f4 * 4);
            int di = row * FSC + f4 * 2;
            sm[FQH + di]     = pack_bf16x2(v.x, v.y);
            sm[FQH + di + 1] = pack_bf16x2(v.z, v.w);
        }
    }

    float o[8][4];
#pragma unroll
    for (int dt = 0; dt < 8; dt++)
#pragma unroll
        for (int e = 0; e < 4; e++) o[dt][e] = 0.0f;
    float m0 = -1e30f, m1 = -1e30f, l0 = 0.0f, l1 = 0.0f;

    const int prow = tid >> 2;
    const float* vrow = Vt + ((((size_t)b * NHEADS + h) * DHEAD) + prow) * SEQ;
    const int qr = wid * 16 + g;

    for (int jb = 0; jb < SEQ; jb += 64) {
        __syncthreads();
        const float* kp = Kg + (bh + jb + prow) * DHEAD;
#pragma unroll
        for (int i = 0; i < 4; i++) {
            int f4 = (tid & 3) + i * 4;
            int di = prow * FSC + f4 * 2;
            float4 v = *(const float4*)(kp + f4 * 4);
            uint32_t h0, lo0, h1, lo1;
            split2(v.x, v.y, h0, lo0);
            split2(v.z, v.w, h1, lo1);
            sm[FKH + di] = h0;  sm[FKH + di + 1] = h1;
            sm[FKL + di] = lo0; sm[FKL + di + 1] = lo1;
            float4 w = *(const float4*)(vrow + jb + f4 * 4);
            split2(w.x, w.y, h0, lo0);
            split2(w.z, w.w, h1, lo1);
            sm[FVH + di] = h0;  sm[FVH + di + 1] = h1;
            sm[FVL + di] = lo0; sm[FVL + di + 1] = lo1;
        }
        __syncthreads();

        // ---- S = Q @ K^T (2 passes: qh*kh + qh*kl) ----
        float s[8][4];
#pragma unroll
        for (int nt = 0; nt < 8; nt++)
#pragma unroll
            for (int e = 0; e < 4; e++) s[nt][e] = 0.0f;

#pragma unroll
        for (int ks = 0; ks < 4; ks++) {
            uint32_t qh[4];
            int qi = qr * FSC + ks * 8 + cq;
            qh[0] = sm[FQH + qi];            qh[1] = sm[FQH + qi + 8 * FSC];
            qh[2] = sm[FQH + qi + 4];        qh[3] = sm[FQH + qi + 8 * FSC + 4];
            uint32_t kh[8][2], kl[8][2];
#pragma unroll
            for (int nt = 0; nt < 8; nt++) {
                int ki = (nt * 8 + g) * FSC + ks * 8 + cq;
                kh[nt][0] = sm[FKH + ki]; kh[nt][1] = sm[FKH + ki + 4];
                kl[nt][0] = sm[FKL + ki]; kl[nt][1] = sm[FKL + ki + 4];
            }
#pragma unroll
            for (int nt = 0; nt < 8; nt++) mma_bf16(s[nt], qh, kh[nt]);
#pragma unroll
            for (int nt = 0; nt < 8; nt++) mma_bf16(s[nt], qh, kl[nt]);
        }

        // ---- online softmax (base 2) ----
        float rm0 = -1e30f, rm1 = -1e30f;
#pragma unroll
        for (int nt = 0; nt < 8; nt++) {
            rm0 = fmaxf(rm0, fmaxf(s[nt][0], s[nt][1]));
            rm1 = fmaxf(rm1, fmaxf(s[nt][2], s[nt][3]));
        }
        rm0 = fmaxf(rm0, __shfl_xor_sync(0xffffffffu, rm0, 1));
        rm0 = fmaxf(rm0, __shfl_xor_sync(0xffffffffu, rm0, 2));
        rm1 = fmaxf(rm1, __shfl_xor_sync(0xffffffffu, rm1, 1));
        rm1 = fmaxf(rm1, __shfl_xor_sync(0xffffffffu, rm1, 2));
        float mn0 = fmaxf(m0, rm0), mn1 = fmaxf(m1, rm1);
        float c0 = exp2f(m0 - mn0), c1 = exp2f(m1 - mn1);
        m0 = mn0; m1 = mn1;
        float rs0 = 0.0f, rs1 = 0.0f;
#pragma unroll
        for (int nt = 0; nt < 8; nt++) {
            s[nt][0] = exp2f(s[nt][0] - mn0);
            s[nt][1] = exp2f(s[nt][1] - mn0);
            s[nt][2] = exp2f(s[nt][2] - mn1);
            s[nt][3] = exp2f(s[nt][3] - mn1);
            rs0 += s[nt][0] + s[nt][1];
            rs1 += s[nt][2] + s[nt][3];
        }
        rs0 += __shfl_xor_sync(0xffffffffu, rs0, 1);
        rs0 += __shfl_xor_sync(0xffffffffu, rs0, 2);
        rs1 += __shfl_xor_sync(0xffffffffu, rs1, 1);
        rs1 += __shfl_xor_sync(0xffffffffu, rs1, 2);
        l0 = l0 * c0 + rs0;
        l1 = l1 * c1 + rs1;
#pragma unroll
        for (int dt = 0; dt < 8; dt++) {
            o[dt][0] *= c0; o[dt][1] *= c0;
            o[dt][2] *= c1; o[dt][3] *= c1;
        }

        // ---- P fragments (plain bf16, no lo) ----
        uint32_t ph[4][4];
#pragma unroll
        for (int kj = 0; kj < 4; kj++) {
            ph[kj][0] = pack_bf16x2(s[2*kj][0],   s[2*kj][1]);
            ph[kj][1] = pack_bf16x2(s[2*kj][2],   s[2*kj][3]);
            ph[kj][2] = pack_bf16x2(s[2*kj+1][0], s[2*kj+1][1]);
            ph[kj][3] = pack_bf16x2(s[2*kj+1][2], s[2*kj+1][3]);
        }

        // ---- O += P @ V (2 passes: ph*vh + ph*vl) ----
#pragma unroll
        for (int kj = 0; kj < 4; kj++) {
            uint32_t vh[8][2], vl[8][2];
#pragma unroll
            for (int dt = 0; dt < 8; dt++) {
                int vi = (dt * 8 + g) * FSC + kj * 8 + cq;
                vh[dt][0] = sm[FVH + vi]; vh[dt][1] = sm[FVH + vi + 4];
                vl[dt][0] = sm[FVL + vi]; vl[dt][1] = sm[FVL + vi + 4];
            }
#pragma unroll
            for (int dt = 0; dt < 8; dt++) mma_bf16(o[dt], ph[kj], vh[dt]);
#pragma unroll
            for (int dt = 0; dt < 8; dt++) mma_bf16(o[dt], ph[kj], vl[dt]);
        }
    }

    // ---- write O ----
    float inv0 = 1.0f / l0, inv1 = 1.0f / l1;
    int row0 = t0 + wid * 16 + g;
#pragma unroll
    for (int dt = 0; dt < 8; dt++) {
        int col = h * DHEAD + dt * 8 + 2 * cq;
        *(float2*)(O + ((size_t)b * SEQ + row0) * DMODEL + col) =
            make_float2(o[dt][0] * inv0, o[dt][1] * inv0);
        *(float2*)(O + ((size_t)b * SEQ + row0 + 8) * DMODEL + col) =
            make_float2(o[dt][2] * inv1, o[dt][3] * inv1);
    }
}

// ---------------------------------------------------------------------------
// out = LayerNorm(a + resid) * g + bias
// ---------------------------------------------------------------------------
__global__ void __launch_bounds__(128) add_ln_k(
    const float* __restrict__ A, const float* __restrict__ R,
    const float* __restrict__ g, const float* __restrict__ bb,
    float* __restrict__ out)
{
    __shared__ float red[4];
    int row = blockIdx.x;
    int tid = threadIdx.x;
    int warp = tid >> 5, lane = tid & 31;

    float4 a4 = *(const float4*)(A + (size_t)row * DMODEL + tid * 4);
    float4 r4 = *(const float4*)(R + (size_t)row * DMODEL + tid * 4);
    float x0 = a4.x + r4.x, x1 = a4.y + r4.y, x2 = a4.z + r4.z, x3 = a4.w + r4.w;

    float s = x0 + x1 + x2 + x3;
    s += __shfl_xor_sync(0xffffffffu, s, 16);
    s += __shfl_xor_sync(0xffffffffu, s, 8);
    s += __shfl_xor_sync(0xffffffffu, s, 4);
    s += __shfl_xor_sync(0xffffffffu, s, 2);
    s += __shfl_xor_sync(0xffffffffu, s, 1);
    if (lane == 0) red[warp] = s;
    __syncthreads();
    float mu = (red[0] + red[1] + red[2] + red[3]) * (1.0f / DMODEL);
    __syncthreads();

    float d0 = x0 - mu, d1 = x1 - mu, d2 = x2 - mu, d3 = x3 - mu;
    float s2 = d0*d0 + d1*d1 + d2*d2 + d3*d3;
    s2 += __shfl_xor_sync(0xffffffffu, s2, 16);
    s2 += __shfl_xor_sync(0xffffffffu, s2, 8);
    s2 += __shfl_xor_sync(0xffffffffu, s2, 4);
    s2 += __shfl_xor_sync(0xffffffffu, s2, 2);
    s2 += __shfl_xor_sync(0xffffffffu, s2, 1);
    if (lane == 0) red[warp] = s2;
    __syncthreads();
    float var = (red[0] + red[1] + red[2] + red[3]) * (1.0f / DMODEL);
    float rstd = rsqrtf(var + 1e-5f);

    float4 gv = *(const float4*)(g  + tid * 4);
    float4 bv = *(const float4*)(bb + tid * 4);
    float4 ov = make_float4(d0 * rstd * gv.x + bv.x,
                            d1 * rstd * gv.y + bv.y,
                            d2 * rstd * gv.z + bv.z,
                            d3 * rstd * gv.w + bv.w);
    *(float4*)(out + (size_t)row * DMODEL + tid * 4) = ov;
}

// ---------------------------------------------------------------------------
// Head
// ---------------------------------------------------------------------------
__global__ void head_k(const float* __restrict__ H, const float* __restrict__ W,
                       const float* __restrict__ bh, float* __restrict__ out)
{
    int gw   = (blockIdx.x * blockDim.x + threadIdx.x) >> 5;
    int lane = threadIdx.x & 31;
    const float* r = H + (size_t)gw * DMODEL;
    float s = 0.0f;
#pragma unroll
    for (int k = 0; k < DMODEL / 32; k++)
        s = fmaf(r[lane + k * 32], W[lane + k * 32], s);
    s += __shfl_xor_sync(0xffffffffu, s, 16);
    s += __shfl_xor_sync(0xffffffffu, s, 8);
    s += __shfl_xor_sync(0xffffffffu, s, 4);
    s += __shfl_xor_sync(0xffffffffu, s, 2);
    s += __shfl_xor_sync(0xffffffffu, s, 1);
    if (lane == 0) out[gw] = s + bh[0];
}

// ---------------------------------------------------------------------------
// Launcher
// ---------------------------------------------------------------------------
extern "C" void kernel_launch(void* const* d_in, const int* in_sizes, int n_in,
                              void* d_out, int out_size)
{
    const int*   x     = (const int*)  d_in[0];
    const float* embed = (const float*)d_in[1];
    const float* pe    = (const float*)d_in[2];
    const float* Wqkv  = (const float*)d_in[3];
    const float* W0    = (const float*)d_in[4];
    const float* g1    = (const float*)d_in[5];
    const float* b1    = (const float*)d_in[6];
    const float* g2    = (const float*)d_in[7];
    const float* b2    = (const float*)d_in[8];
    const float* Wl1   = (const float*)d_in[9];
    const float* bl1   = (const float*)d_in[10];
    const float* Wl2   = (const float*)d_in[11];
    const float* bl2   = (const float*)d_in[12];
    const float* Wh    = (const float*)d_in[13];
    const float* bh    = (const float*)d_in[14];
    float* out = (float*)d_out;

    float *hb, *yb, *ab, *aob, *qb, *kb, *vb, *midb;
    float *wtqkv, *wt0, *wt1, *wt2;
    cudaGetSymbolAddress((void**)&hb,    g_h);
    cudaGetSymbolAddress((void**)&yb,    g_y);
    cudaGetSymbolAddress((void**)&ab,    g_a);
    cudaGetSymbolAddress((void**)&aob,   g_ao);
    cudaGetSymbolAddress((void**)&qb,    g_q);
    cudaGetSymbolAddress((void**)&kb,    g_k);
    cudaGetSymbolAddress((void**)&vb,    g_v);
    cudaGetSymbolAddress((void**)&midb,  g_mid);
    cudaGetSymbolAddress((void**)&wtqkv, g_wt_qkv);
    cudaGetSymbolAddress((void**)&wt0,   g_wt_w0);
    cudaGetSymbolAddress((void**)&wt1,   g_wt_l1);
    cudaGetSymbolAddress((void**)&wt2,   g_wt_l2);

    cudaFuncSetAttribute(flash_mma, cudaFuncAttributeMaxDynamicSharedMemorySize,
                         FLASH2_SMEM);
    cudaFuncSetAttribute(gemm_mma<0>, cudaFuncAttributeMaxDynamicSharedMemorySize, GMM_SMEM);
    cudaFuncSetAttribute(gemm_mma<1>, cudaFuncAttributeMaxDynamicSharedMemorySize, GMM_SMEM);
    cudaFuncSetAttribute(gemm_mma<2>, cudaFuncAttributeMaxDynamicSharedMemorySize, GMM_SMEM);
    cudaFuncSetAttribute(gemm_mma<3>, cudaFuncAttributeMaxDynamicSharedMemorySize, GMM_SMEM);

    wqkvtrans_k<<<dim3((1536 * 512) / 256, NBLOCKS), 256>>>(Wqkv, wtqkv);
    wtrans_k<<<dim3(16, 16, NBLOCKS), dim3(32, 8)>>>(W0,  wt0, DMODEL, DMODEL);
    wtrans_k<<<dim3(64, 16, NBLOCKS), dim3(32, 8)>>>(Wl1, wt1, DMODEL, DFF);
    wtrans_k<<<dim3(16, 64, NBLOCKS), dim3(32, 8)>>>(Wl2, wt2, DFF, DMODEL);

    embed_k<<<(NROWS * (DMODEL / 4)) / 256, 256>>>(x, embed, pe, hb);

    for (int i = 0; i < NBLOCKS; i++) {
        gemm_mma<3><<<dim3(12, 64), 256, GMM_SMEM>>>(
            hb, wtqkv + (size_t)i * 1536 * 512, nullptr, nullptr,
            qb, kb, vb, NROWS, 3 * DMODEL, DMODEL);

        flash_mma<<<dim3(SEQ / 128, NHEADS, BATCH), 256, FLASH2_SMEM>>>(qb, kb, vb, aob);

        gemm_mma<0><<<dim3(4, 64), 256, GMM_SMEM>>>(
            aob, wt0 + (size_t)i * DMODEL * DMODEL, nullptr, ab,
            nullptr, nullptr, nullptr, NROWS, DMODEL, DMODEL);

        add_ln_k<<<NROWS, 128>>>(ab, hb, g1 + i * DMODEL, b1 + i * DMODEL, yb);

        gemm_mma<2><<<dim3(16, 64), 256, GMM_SMEM>>>(
            yb, wt1 + (size_t)i * DFF * DMODEL, bl1 + i * DFF, midb,
            nullptr, nullptr, nullptr, NROWS, DFF, DMODEL);

        gemm_mma<1><<<dim3(4, 64), 256, GMM_SMEM>>>(
            midb, wt2 + (size_t)i * DMODEL * DFF, bl2 + i * DMODEL, ab,
            nullptr, nullptr, nullptr, NROWS, DMODEL, DFF);

        add_ln_k<<<NROWS, 128>>>(ab, yb, g2 + i * DMODEL, b2 + i * DMODEL, hb);
    }

    head_k<<<NROWS / 8, 256>>>(hb, Wh, bh, out);
}

// round 17
// speedup vs baseline: 1.2443x; 1.1057x over previous
#include <cuda_runtime.h>
#include <cuda_bf16.h>
#include <cstdint>
#include <math.h>

// Problem constants
#define BATCH  4
#define SEQ    2048
#define DMODEL 512
#define NHEADS 8
#define DHEAD  64
#define DFF    2048
#define NBLOCKS 6
#define NROWS  (BATCH * SEQ)   // 8192

// ---------------------------------------------------------------------------
// Scratch (device globals)
// ---------------------------------------------------------------------------
__device__ float g_h  [NROWS * DMODEL];
__device__ float g_y  [NROWS * DMODEL];
__device__ float g_a  [NROWS * DMODEL];
__device__ float g_ao [NROWS * DMODEL];
__device__ float g_q  [BATCH * NHEADS * SEQ * DHEAD];
__device__ float g_k  [BATCH * NHEADS * SEQ * DHEAD];
__device__ float g_v  [BATCH * NHEADS * DHEAD * SEQ];   // transposed [B,H,D,T]
__device__ float g_mid[NROWS * DFF];
// Transposed weights, [N][K] K-major
__device__ float g_wt_qkv[NBLOCKS * 3 * DMODEL * DMODEL];
__device__ float g_wt_w0 [NBLOCKS * DMODEL * DMODEL];
__device__ float g_wt_l1 [NBLOCKS * DFF * DMODEL];
__device__ float g_wt_l2 [NBLOCKS * DMODEL * DFF];

__device__ __forceinline__ float gelu_exact(float x) {
    return 0.5f * x * (1.0f + erff(x * 0.70710678118654752f));
}

// ---------------------------------------------------------------------------
// bf16 split: x = hi + lo
// ---------------------------------------------------------------------------
__device__ __forceinline__ void split2(float x, float y, uint32_t& hi, uint32_t& lo) {
    __nv_bfloat16 hx = __float2bfloat16_rn(x);
    __nv_bfloat16 hy = __float2bfloat16_rn(y);
    float rx = x - __bfloat162float(hx);
    float ry = y - __bfloat162float(hy);
    __nv_bfloat162 H; H.x = hx; H.y = hy;
    __nv_bfloat162 L = __floats2bfloat162_rn(rx, ry);
    hi = *reinterpret_cast<uint32_t*>(&H);
    lo = *reinterpret_cast<uint32_t*>(&L);
}

__device__ __forceinline__ uint32_t pack_bf16x2(float x, float y) {
    __nv_bfloat162 H = __floats2bfloat162_rn(x, y);
    return *reinterpret_cast<uint32_t*>(&H);
}

__device__ __forceinline__ void mma_bf16(float* c, const uint32_t* a, const uint32_t* b) {
    asm volatile(
        "mma.sync.aligned.m16n8k16.row.col.f32.bf16.bf16.f32 "
        "{%0,%1,%2,%3}, {%4,%5,%6,%7}, {%8,%9}, {%0,%1,%2,%3};"
        : "+f"(c[0]), "+f"(c[1]), "+f"(c[2]), "+f"(c[3])
        : "r"(a[0]), "r"(a[1]), "r"(a[2]), "r"(a[3]), "r"(b[0]), "r"(b[1]));
}

// ---------------------------------------------------------------------------
// Embedding + sinusoidal PE
// ---------------------------------------------------------------------------
__global__ void embed_k(const int* __restrict__ x, const float* __restrict__ E,
                        const float* __restrict__ pe, float* __restrict__ H) {
    int idx = blockIdx.x * blockDim.x + threadIdx.x;
    int row = idx >> 7;
    int c   = (idx & 127) << 2;
    int t   = row & (SEQ - 1);
    int tok = x[row];
    float4 e = *(const float4*)(E  + (size_t)tok * DMODEL + c);
    float4 p = *(const float4*)(pe + (size_t)t   * DMODEL + c);
    *(float4*)(H + (size_t)row * DMODEL + c) =
        make_float4(e.x + p.x, e.y + p.y, e.z + p.z, e.w + p.w);
}

// ---------------------------------------------------------------------------
// Weight transposes
// ---------------------------------------------------------------------------
__global__ void wtrans_k(const float* __restrict__ W, float* __restrict__ Wt,
                         int K, int N) {
    __shared__ float t[32][33];
    int n0 = blockIdx.x * 32, k0 = blockIdx.y * 32;
    const float* Wz = W  + (size_t)blockIdx.z * K * N;
    float*      Wtz = Wt + (size_t)blockIdx.z * K * N;
    int tx = threadIdx.x, ty = threadIdx.y;
#pragma unroll
    for (int i = 0; i < 32; i += 8)
        t[ty + i][tx] = Wz[(size_t)(k0 + ty + i) * N + n0 + tx];
    __syncthreads();
#pragma unroll
    for (int i = 0; i < 32; i += 8)
        Wtz[(size_t)(n0 + ty + i) * K + k0 + tx] = t[tx][ty + i];
}

__global__ void wqkvtrans_k(const float* __restrict__ W, float* __restrict__ Wt) {
    int z   = blockIdx.y;
    int idx = blockIdx.x * 256 + threadIdx.x;
    int k   = idx & 511;
    int np  = idx >> 9;
    int kv  = np >> 9, h = (np >> 6) & 7, d = np & 63;
    int n   = d * 24 + kv * 8 + h;
    float w = W[((size_t)z * 512 + k) * 1536 + n];
    if (kv == 0) w *= 0.18033688011112042f;   // fold 0.125*log2(e) into Q
    Wt[(size_t)z * 1536 * 512 + idx] = w;
}

// ---------------------------------------------------------------------------
// bf16x3 warp-MMA GEMM (round-5/14 proven, unchanged)
// EPI: 0 plain, 1 +bias, 2 +bias+gelu, 3 QKV scatter (V transposed)
// ---------------------------------------------------------------------------
#define GST 10240
#define GMM_SMEM (2 * GST * 4)

template <int EPI>
__global__ void __launch_bounds__(256) gemm_mma(
    const float* __restrict__ A, const float* __restrict__ Bt,
    const float* __restrict__ bias, float* __restrict__ C,
    float* __restrict__ Qo, float* __restrict__ Ko, float* __restrict__ Vo,
    int M, int N, int K)
{
    extern __shared__ uint32_t sm[];

    const int tid  = threadIdx.x;
    const int wid  = tid >> 5;
    const int lane = tid & 31;
    const int g    = lane >> 2;
    const int cq   = lane & 3;
    const int wm   = (wid & 1) * 64;
    const int wn   = (wid >> 1) * 32;
    const int m0   = blockIdx.y * 128;
    const int n0   = blockIdx.x * 128;

    const int col4 = tid & 7;
    const int rb   = tid >> 3;

    const float* Ap = A  + (size_t)(m0 + rb) * K + col4 * 4;
    const float* Bp = Bt + (size_t)(n0 + rb) * K + col4 * 4;

    float acc[4][4][4];
#pragma unroll
    for (int mt = 0; mt < 4; mt++)
#pragma unroll
        for (int nt = 0; nt < 4; nt++)
#pragma unroll
            for (int e = 0; e < 4; e++) acc[mt][nt][e] = 0.0f;

    const int NC = K >> 5;

    float4 pa[4], pb[4];
#pragma unroll
    for (int i = 0; i < 4; i++) {
        pa[i] = *(const float4*)(Ap + (size_t)(32 * i) * K);
        pb[i] = *(const float4*)(Bp + (size_t)(32 * i) * K);
    }

    for (int c = 0; c < NC; c++) {
        const int p = c & 1;
        uint32_t* sp = sm + p * GST;

#pragma unroll
        for (int i = 0; i < 4; i++) {
            int di = (rb + 32 * i) * 20 + col4 * 2;
            uint32_t h0, l0, h1, l1;
            split2(pa[i].x, pa[i].y, h0, l0);
            split2(pa[i].z, pa[i].w, h1, l1);
            *reinterpret_cast<uint2*>(sp + di)        = make_uint2(h0, h1);
            *reinterpret_cast<uint2*>(sp + 2560 + di) = make_uint2(l0, l1);
            split2(pb[i].x, pb[i].y, h0, l0);
            split2(pb[i].z, pb[i].w, h1, l1);
            *reinterpret_cast<uint2*>(sp + 5120 + di) = make_uint2(h0, h1);
            *reinterpret_cast<uint2*>(sp + 7680 + di) = make_uint2(l0, l1);
        }
        __syncthreads();

        if (c + 1 < NC) {
            const float* Apn = Ap + (c + 1) * 32;
            const float* Bpn = Bp + (c + 1) * 32;
#pragma unroll
            for (int i = 0; i < 4; i++) {
                pa[i] = *(const float4*)(Apn + (size_t)(32 * i) * K);
                pb[i] = *(const float4*)(Bpn + (size_t)(32 * i) * K);
            }
        }

#pragma unroll
        for (int ks = 0; ks < 2; ks++) {
            const int kb = ks * 8;
            uint32_t bh[4][2], bl[4][2];
#pragma unroll
            for (int nt = 0; nt < 4; nt++) {
                int bi = 5120 + (wn + nt * 8 + g) * 20 + kb + cq;
                bh[nt][0] = sp[bi];
                bh[nt][1] = sp[bi + 4];
                bl[nt][0] = sp[bi + 2560];
                bl[nt][1] = sp[bi + 2560 + 4];
            }
#pragma unroll
            for (int mt = 0; mt < 4; mt++) {
                int ai = (wm + mt * 16 + g) * 20 + kb + cq;
                uint32_t ah[4], al[4];
                ah[0] = sp[ai];             ah[1] = sp[ai + 160];
                ah[2] = sp[ai + 4];         ah[3] = sp[ai + 160 + 4];
                al[0] = sp[ai + 2560];      al[1] = sp[ai + 2560 + 160];
                al[2] = sp[ai + 2560 + 4];  al[3] = sp[ai + 2560 + 160 + 4];
#pragma unroll
                for (int nt = 0; nt < 4; nt++) mma_bf16(acc[mt][nt], ah, bh[nt]);
#pragma unroll
                for (int nt = 0; nt < 4; nt++) mma_bf16(acc[mt][nt], al, bh[nt]);
#pragma unroll
                for (int nt = 0; nt < 4; nt++) mma_bf16(acc[mt][nt], ah, bl[nt]);
            }
        }
    }

#pragma unroll
    for (int mt = 0; mt < 4; mt++) {
#pragma unroll
        for (int nt = 0; nt < 4; nt++) {
            int col = n0 + wn + nt * 8 + 2 * cq;
            int r0  = m0 + wm + mt * 16 + g;
            float2 v0 = make_float2(acc[mt][nt][0], acc[mt][nt][1]);
            float2 v1 = make_float2(acc[mt][nt][2], acc[mt][nt][3]);
            if (EPI == 3) {
                int kv = col >> 9, h = (col >> 6) & 7, d = col & 63;
                int b0i = r0 >> 11, t0i = r0 & (SEQ - 1);
                int r1 = r0 + 8;
                int b1i = r1 >> 11, t1i = r1 & (SEQ - 1);
                if (kv == 2) {
                    size_t base0 = (((size_t)b0i * NHEADS + h) * DHEAD + d) * SEQ;
                    size_t base1 = (((size_t)b1i * NHEADS + h) * DHEAD + d) * SEQ;
                    Vo[base0 + t0i]       = v0.x;
                    Vo[base0 + SEQ + t0i] = v0.y;
                    Vo[base1 + t1i]       = v1.x;
                    Vo[base1 + SEQ + t1i] = v1.y;
                } else {
                    float* dst = (kv == 0) ? Qo : Ko;
                    *(float2*)(dst + (((size_t)b0i * NHEADS + h) * SEQ + t0i) * DHEAD + d) = v0;
                    *(float2*)(dst + (((size_t)b1i * NHEADS + h) * SEQ + t1i) * DHEAD + d) = v1;
                }
            } else {
                if (EPI >= 1) {
                    float2 bb = *(const float2*)(bias + col);
                    v0.x += bb.x; v0.y += bb.y;
                    v1.x += bb.x; v1.y += bb.y;
                }
                if (EPI == 2) {
                    v0.x = gelu_exact(v0.x); v0.y = gelu_exact(v0.y);
                    v1.x = gelu_exact(v1.x); v1.y = gelu_exact(v1.y);
                }
                *(float2*)(C + (size_t)r0 * N + col)       = v0;
                *(float2*)(C + (size_t)(r0 + 8) * N + col) = v1;
            }
        }
    }
}

// ---------------------------------------------------------------------------
// Flash attention, pure-bf16 mma.sync (single pass per GEMM).
// S = Qh·Kh, O = Ph·Vh.  Errors are diluted in the residual stream
// (measured: dropping Q-lo/P-lo cost only +2.3e-5 rel_err).
// CTA = 128 queries x 64-key blocks, 8 warps.  Smem stride 36 u32.
// Q prescaled by 0.125*log2(e) (folded into Wq).
// ---------------------------------------------------------------------------
#define FSC 36
#define FQH 0
#define FKH 4608
#define FVH 6912
#define FLASH2_SMEM (9216 * 4)

__global__ void __launch_bounds__(256, 2) flash_mma(
    const float* __restrict__ Q, const float* __restrict__ Kg,
    const float* __restrict__ Vt, float* __restrict__ O)
{
    extern __shared__ uint32_t sm[];
    const int tid  = threadIdx.x;
    const int wid  = tid >> 5;
    const int lane = tid & 31;
    const int g    = lane >> 2;
    const int cq   = lane & 3;
    const int t0   = blockIdx.x * 128;
    const int h    = blockIdx.y;
    const int b    = blockIdx.z;
    const size_t bh = ((size_t)b * NHEADS + h) * SEQ;

    // ---- load Q (prescaled in weights; plain bf16) ----
    {
        int row = tid >> 1;
        const float* qp = Q + (bh + t0 + row) * DHEAD;
#pragma unroll
        for (int i = 0; i < 8; i++) {
            int f4 = (tid & 1) + 2 * i;
            float4 v = *(const float4*)(qp + f4 * 4);
            int di = row * FSC + f4 * 2;
            sm[FQH + di]     = pack_bf16x2(v.x, v.y);
            sm[FQH + di + 1] = pack_bf16x2(v.z, v.w);
        }
    }

    float o[8][4];
#pragma unroll
    for (int dt = 0; dt < 8; dt++)
#pragma unroll
        for (int e = 0; e < 4; e++) o[dt][e] = 0.0f;
    float m0 = -1e30f, m1 = -1e30f, l0 = 0.0f, l1 = 0.0f;

    const int prow = tid >> 2;
    const float* vrow = Vt + ((((size_t)b * NHEADS + h) * DHEAD) + prow) * SEQ;
    const int qr = wid * 16 + g;

    for (int jb = 0; jb < SEQ; jb += 64) {
        __syncthreads();
        const float* kp = Kg + (bh + jb + prow) * DHEAD;
#pragma unroll
        for (int i = 0; i < 4; i++) {
            int f4 = (tid & 3) + i * 4;
            int di = prow * FSC + f4 * 2;
            float4 v = *(const float4*)(kp + f4 * 4);
            sm[FKH + di]     = pack_bf16x2(v.x, v.y);
            sm[FKH + di + 1] = pack_bf16x2(v.z, v.w);
            float4 w = *(const float4*)(vrow + jb + f4 * 4);
            sm[FVH + di]     = pack_bf16x2(w.x, w.y);
            sm[FVH + di + 1] = pack_bf16x2(w.z, w.w);
        }
        __syncthreads();

        // ---- S = Q @ K^T (single bf16 pass) ----
        float s[8][4];
#pragma unroll
        for (int nt = 0; nt < 8; nt++)
#pragma unroll
            for (int e = 0; e < 4; e++) s[nt][e] = 0.0f;

#pragma unroll
        for (int ks = 0; ks < 4; ks++) {
            uint32_t qh[4];
            int qi = qr * FSC + ks * 8 + cq;
            qh[0] = sm[FQH + qi];            qh[1] = sm[FQH + qi + 8 * FSC];
            qh[2] = sm[FQH + qi + 4];        qh[3] = sm[FQH + qi + 8 * FSC + 4];
            uint32_t kh[8][2];
#pragma unroll
            for (int nt = 0; nt < 8; nt++) {
                int ki = (nt * 8 + g) * FSC + ks * 8 + cq;
                kh[nt][0] = sm[FKH + ki]; kh[nt][1] = sm[FKH + ki + 4];
            }
#pragma unroll
            for (int nt = 0; nt < 8; nt++) mma_bf16(s[nt], qh, kh[nt]);
        }

        // ---- online softmax (base 2) ----
        float rm0 = -1e30f, rm1 = -1e30f;
#pragma unroll
        for (int nt = 0; nt < 8; nt++) {
            rm0 = fmaxf(rm0, fmaxf(s[nt][0], s[nt][1]));
            rm1 = fmaxf(rm1, fmaxf(s[nt][2], s[nt][3]));
        }
        rm0 = fmaxf(rm0, __shfl_xor_sync(0xffffffffu, rm0, 1));
        rm0 = fmaxf(rm0, __shfl_xor_sync(0xffffffffu, rm0, 2));
        rm1 = fmaxf(rm1, __shfl_xor_sync(0xffffffffu, rm1, 1));
        rm1 = fmaxf(rm1, __shfl_xor_sync(0xffffffffu, rm1, 2));
        float mn0 = fmaxf(m0, rm0), mn1 = fmaxf(m1, rm1);
        float c0 = exp2f(m0 - mn0), c1 = exp2f(m1 - mn1);
        m0 = mn0; m1 = mn1;
        float rs0 = 0.0f, rs1 = 0.0f;
#pragma unroll
        for (int nt = 0; nt < 8; nt++) {
            s[nt][0] = exp2f(s[nt][0] - mn0);
            s[nt][1] = exp2f(s[nt][1] - mn0);
            s[nt][2] = exp2f(s[nt][2] - mn1);
            s[nt][3] = exp2f(s[nt][3] - mn1);
            rs0 += s[nt][0] + s[nt][1];
            rs1 += s[nt][2] + s[nt][3];
        }
        rs0 += __shfl_xor_sync(0xffffffffu, rs0, 1);
        rs0 += __shfl_xor_sync(0xffffffffu, rs0, 2);
        rs1 += __shfl_xor_sync(0xffffffffu, rs1, 1);
        rs1 += __shfl_xor_sync(0xffffffffu, rs1, 2);
        l0 = l0 * c0 + rs0;
        l1 = l1 * c1 + rs1;
#pragma unroll
        for (int dt = 0; dt < 8; dt++) {
            o[dt][0] *= c0; o[dt][1] *= c0;
            o[dt][2] *= c1; o[dt][3] *= c1;
        }

        // ---- P fragments (plain bf16) ----
        uint32_t ph[4][4];
#pragma unroll
        for (int kj = 0; kj < 4; kj++) {
            ph[kj][0] = pack_bf16x2(s[2*kj][0],   s[2*kj][1]);
            ph[kj][1] = pack_bf16x2(s[2*kj][2],   s[2*kj][3]);
            ph[kj][2] = pack_bf16x2(s[2*kj+1][0], s[2*kj+1][1]);
            ph[kj][3] = pack_bf16x2(s[2*kj+1][2], s[2*kj+1][3]);
        }

        // ---- O += P @ V (single bf16 pass) ----
#pragma unroll
        for (int kj = 0; kj < 4; kj++) {
            uint32_t vh[8][2];
#pragma unroll
            for (int dt = 0; dt < 8; dt++) {
                int vi = (dt * 8 + g) * FSC + kj * 8 + cq;
                vh[dt][0] = sm[FVH + vi]; vh[dt][1] = sm[FVH + vi + 4];
            }
#pragma unroll
            for (int dt = 0; dt < 8; dt++) mma_bf16(o[dt], ph[kj], vh[dt]);
        }
    }

    // ---- write O ----
    float inv0 = 1.0f / l0, inv1 = 1.0f / l1;
    int row0 = t0 + wid * 16 + g;
#pragma unroll
    for (int dt = 0; dt < 8; dt++) {
        int col = h * DHEAD + dt * 8 + 2 * cq;
        *(float2*)(O + ((size_t)b * SEQ + row0) * DMODEL + col) =
            make_float2(o[dt][0] * inv0, o[dt][1] * inv0);
        *(float2*)(O + ((size_t)b * SEQ + row0 + 8) * DMODEL + col) =
            make_float2(o[dt][2] * inv1, o[dt][3] * inv1);
    }
}

// ---------------------------------------------------------------------------
// out = LayerNorm(a + resid) * g + bias
// ---------------------------------------------------------------------------
__global__ void __launch_bounds__(128) add_ln_k(
    const float* __restrict__ A, const float* __restrict__ R,
    const float* __restrict__ g, const float* __restrict__ bb,
    float* __restrict__ out)
{
    __shared__ float red[4];
    int row = blockIdx.x;
    int tid = threadIdx.x;
    int warp = tid >> 5, lane = tid & 31;

    float4 a4 = *(const float4*)(A + (size_t)row * DMODEL + tid * 4);
    float4 r4 = *(const float4*)(R + (size_t)row * DMODEL + tid * 4);
    float x0 = a4.x + r4.x, x1 = a4.y + r4.y, x2 = a4.z + r4.z, x3 = a4.w + r4.w;

    float s = x0 + x1 + x2 + x3;
    s += __shfl_xor_sync(0xffffffffu, s, 16);
    s += __shfl_xor_sync(0xffffffffu, s, 8);
    s += __shfl_xor_sync(0xffffffffu, s, 4);
    s += __shfl_xor_sync(0xffffffffu, s, 2);
    s += __shfl_xor_sync(0xffffffffu, s, 1);
    if (lane == 0) red[warp] = s;
    __syncthreads();
    float mu = (red[0] + red[1] + red[2] + red[3]) * (1.0f / DMODEL);
    __syncthreads();

    float d0 = x0 - mu, d1 = x1 - mu, d2 = x2 - mu, d3 = x3 - mu;
    float s2 = d0*d0 + d1*d1 + d2*d2 + d3*d3;
    s2 += __shfl_xor_sync(0xffffffffu, s2, 16);
    s2 += __shfl_xor_sync(0xffffffffu, s2, 8);
    s2 += __shfl_xor_sync(0xffffffffu, s2, 4);
    s2 += __shfl_xor_sync(0xffffffffu, s2, 2);
    s2 += __shfl_xor_sync(0xffffffffu, s2, 1);
    if (lane == 0) red[warp] = s2;
    __syncthreads();
    float var = (red[0] + red[1] + red[2] + red[3]) * (1.0f / DMODEL);
    float rstd = rsqrtf(var + 1e-5f);

    float4 gv = *(const float4*)(g  + tid * 4);
    float4 bv = *(const float4*)(bb + tid * 4);
    float4 ov = make_float4(d0 * rstd * gv.x + bv.x,
                            d1 * rstd * gv.y + bv.y,
                            d2 * rstd * gv.z + bv.z,
                            d3 * rstd * gv.w + bv.w);
    *(float4*)(out + (size_t)row * DMODEL + tid * 4) = ov;
}

// ---------------------------------------------------------------------------
// Head
// ---------------------------------------------------------------------------
__global__ void head_k(const float* __restrict__ H, const float* __restrict__ W,
                       const float* __restrict__ bh, float* __restrict__ out)
{
    int gw   = (blockIdx.x * blockDim.x + threadIdx.x) >> 5;
    int lane = threadIdx.x & 31;
    const float* r = H + (size_t)gw * DMODEL;
    float s = 0.0f;
#pragma unroll
    for (int k = 0; k < DMODEL / 32; k++)
        s = fmaf(r[lane + k * 32], W[lane + k * 32], s);
    s += __shfl_xor_sync(0xffffffffu, s, 16);
    s += __shfl_xor_sync(0xffffffffu, s, 8);
    s += __shfl_xor_sync(0xffffffffu, s, 4);
    s += __shfl_xor_sync(0xffffffffu, s, 2);
    s += __shfl_xor_sync(0xffffffffu, s, 1);
    if (lane == 0) out[gw] = s + bh[0];
}

// ---------------------------------------------------------------------------
// Launcher
// ---------------------------------------------------------------------------
extern "C" void kernel_launch(void* const* d_in, const int* in_sizes, int n_in,
                              void* d_out, int out_size)
{
    const int*   x     = (const int*)  d_in[0];
    const float* embed = (const float*)d_in[1];
    const float* pe    = (const float*)d_in[2];
    const float* Wqkv  = (const float*)d_in[3];
    const float* W0    = (const float*)d_in[4];
    const float* g1    = (const float*)d_in[5];
    const float* b1    = (const float*)d_in[6];
    const float* g2    = (const float*)d_in[7];
    const float* b2    = (const float*)d_in[8];
    const float* Wl1   = (const float*)d_in[9];
    const float* bl1   = (const float*)d_in[10];
    const float* Wl2   = (const float*)d_in[11];
    const float* bl2   = (const float*)d_in[12];
    const float* Wh    = (const float*)d_in[13];
    const float* bh    = (const float*)d_in[14];
    float* out = (float*)d_out;

    float *hb, *yb, *ab, *aob, *qb, *kb, *vb, *midb;
    float *wtqkv, *wt0, *wt1, *wt2;
    cudaGetSymbolAddress((void**)&hb,    g_h);
    cudaGetSymbolAddress((void**)&yb,    g_y);
    cudaGetSymbolAddress((void**)&ab,    g_a);
    cudaGetSymbolAddress((void**)&aob,   g_ao);
    cudaGetSymbolAddress((void**)&qb,    g_q);
    cudaGetSymbolAddress((void**)&kb,    g_k);
    cudaGetSymbolAddress((void**)&vb,    g_v);
    cudaGetSymbolAddress((void**)&midb,  g_mid);
    cudaGetSymbolAddress((void**)&wtqkv, g_wt_qkv);
    cudaGetSymbolAddress((void**)&wt0,   g_wt_w0);
    cudaGetSymbolAddress((void**)&wt1,   g_wt_l1);
    cudaGetSymbolAddress((void**)&wt2,   g_wt_l2);

    cudaFuncSetAttribute(flash_mma, cudaFuncAttributeMaxDynamicSharedMemorySize,
                         FLASH2_SMEM);
    cudaFuncSetAttribute(gemm_mma<0>, cudaFuncAttributeMaxDynamicSharedMemorySize, GMM_SMEM);
    cudaFuncSetAttribute(gemm_mma<1>, cudaFuncAttributeMaxDynamicSharedMemorySize, GMM_SMEM);
    cudaFuncSetAttribute(gemm_mma<2>, cudaFuncAttributeMaxDynamicSharedMemorySize, GMM_SMEM);
    cudaFuncSetAttribute(gemm_mma<3>, cudaFuncAttributeMaxDynamicSharedMemorySize, GMM_SMEM);

    wqkvtrans_k<<<dim3((1536 * 512) / 256, NBLOCKS), 256>>>(Wqkv, wtqkv);
    wtrans_k<<<dim3(16, 16, NBLOCKS), dim3(32, 8)>>>(W0,  wt0, DMODEL, DMODEL);
    wtrans_k<<<dim3(64, 16, NBLOCKS), dim3(32, 8)>>>(Wl1, wt1, DMODEL, DFF);
    wtrans_k<<<dim3(16, 64, NBLOCKS), dim3(32, 8)>>>(Wl2, wt2, DFF, DMODEL);

    embed_k<<<(NROWS * (DMODEL / 4)) / 256, 256>>>(x, embed, pe, hb);

    for (int i = 0; i < NBLOCKS; i++) {
        gemm_mma<3><<<dim3(12, 64), 256, GMM_SMEM>>>(
            hb, wtqkv + (size_t)i * 1536 * 512, nullptr, nullptr,
            qb, kb, vb, NROWS, 3 * DMODEL, DMODEL);

        flash_mma<<<dim3(SEQ / 128, NHEADS, BATCH), 256, FLASH2_SMEM>>>(qb, kb, vb, aob);

        gemm_mma<0><<<dim3(4, 64), 256, GMM_SMEM>>>(
            aob, wt0 + (size_t)i * DMODEL * DMODEL, nullptr, ab,
            nullptr, nullptr, nullptr, NROWS, DMODEL, DMODEL);

        add_ln_k<<<NROWS, 128>>>(ab, hb, g1 + i * DMODEL, b1 + i * DMODEL, yb);

        gemm_mma<2><<<dim3(16, 64), 256, GMM_SMEM>>>(
            yb, wt1 + (size_t)i * DFF * DMODEL, bl1 + i * DFF, midb,
            nullptr, nullptr, nullptr, NROWS, DFF, DMODEL);

        gemm_mma<1><<<dim3(4, 64), 256, GMM_SMEM>>>(
            midb, wt2 + (size_t)i * DMODEL * DFF, bl2 + i * DMODEL, ab,
            nullptr, nullptr, nullptr, NROWS, DMODEL, DFF);

        add_ln_k<<<NROWS, 128>>>(ab, yb, g2 + i * DMODEL, b2 + i * DMODEL, hb);
    }

    head_k<<<NROWS / 8, 256>>>(hb, Wh, bh, out);
}